// round 12
// baseline (speedup 1.0000x reference)
#include <cuda_runtime.h>
#include <cuda_fp16.h>
#include <math.h>
#include <stdint.h>

#define Hh 128
#define Ww 128
#define Cc 128
#define Nn (Hh*Ww)
#define Bb 2
#define NIMG 4          // img = tensor*2 + batch ; tensor 0 = u, 1 = v
#define KK9 9
#define OCH 18
#define NCHUNK 64

// -------- scratch (static device allocations; no runtime alloc allowed) ------
__device__ float g_xnhwc[NIMG][Nn][Cc];   // inputs transposed to NHWC (fp32)
__device__ __half g_xh[NIMG][Nn][Cc];     // x hi-half
__device__ __half g_xl[NIMG][Nn][Cc];     // x lo-half
__device__ float g_off[NIMG][Nn][OCH];    // offset conv output, per-pixel 18 vals
__device__ float g_xd[NIMG][Nn][Cc];      // deformable conv outputs (NHWC)
__device__ __half g_Wh[KK9][Cc][Cc];      // dcn_w hi-half [kk][co][c]
__device__ __half g_Wl[KK9][Cc][Cc];      // dcn_w lo-half
__device__ __half g_Woh[KK9][32][Cc];     // offset_w hi [tap][out(pad32)][c]
__device__ __half g_Wol[KK9][32][Cc];     // offset_w lo
__device__ float g_Gp[Bb][NCHUNK][Cc*Cc]; // Gram partials
__device__ float g_sup[Bb][NCHUNK][Cc];
__device__ float g_svp[Bb][NCHUNK][Cc];
__device__ float g_G[Bb][Cc*Cc];
__device__ float g_su[Bb][Cc];
__device__ float g_sv[Bb][Cc];
__device__ float g_Mt[Bb][Cc*Cc];         // (attn @ Vw)^T  [m][i]
__device__ float g_r[Bb][Cc];             // attn @ vb

// ------------------------------ common helpers -------------------------------
__device__ __forceinline__ void mma16816(float* d, uint32_t a0, uint32_t a1,
                                         uint32_t a2, uint32_t a3,
                                         uint32_t b0, uint32_t b1) {
    asm volatile(
        "mma.sync.aligned.m16n8k16.row.col.f32.f16.f16.f32 "
        "{%0,%1,%2,%3}, {%4,%5,%6,%7}, {%8,%9}, {%0,%1,%2,%3};"
        : "+f"(d[0]), "+f"(d[1]), "+f"(d[2]), "+f"(d[3])
        : "r"(a0), "r"(a1), "r"(a2), "r"(a3), "r"(b0), "r"(b1));
}
__device__ __forceinline__ uint32_t smem_u32(const void* p) {
    uint32_t a;
    asm("{ .reg .u64 t; cvta.to.shared.u64 t, %1; cvt.u32.u64 %0, t; }" : "=r"(a) : "l"(p));
    return a;
}
__device__ __forceinline__ void ldm4(uint32_t* r, uint32_t addr) {
    asm volatile("ldmatrix.sync.aligned.m8n8.x4.shared.b16 {%0,%1,%2,%3}, [%4];"
                 : "=r"(r[0]), "=r"(r[1]), "=r"(r[2]), "=r"(r[3]) : "r"(addr));
}
__device__ __forceinline__ void cp16(uint32_t s, const void* g) {
    asm volatile("cp.async.cg.shared.global [%0], [%1], 16;" :: "r"(s), "l"(g));
}

// ------------------------------ K0: weight prep ------------------------------
__global__ void k0_prep(const float* __restrict__ dcn_w,
                        const float* __restrict__ offset_w) {
    int idx = blockIdx.x * blockDim.x + threadIdx.x;
    if (idx < KK9 * Cc * Cc) {
        int kk = idx / (Cc * Cc);
        int rem = idx % (Cc * Cc);
        int co = rem >> 7, c = rem & 127;
        float w = dcn_w[(co * Cc + c) * KK9 + kk];
        __half h = __float2half_rn(w);
        __half l = __float2half_rn(w - __half2float(h));
        g_Wh[kk][co][c] = h;
        g_Wl[kk][co][c] = l;
    }
    if (idx < KK9 * 32 * Cc) {
        int tap = idx / (32 * Cc);
        int rem = idx % (32 * Cc);
        int o = rem >> 7, c = rem & 127;
        float w = (o < OCH) ? offset_w[(o * Cc + c) * KK9 + tap] : 0.f;
        __half h = __float2half_rn(w);
        __half l = __float2half_rn(w - __half2float(h));
        g_Woh[tap][o][c] = h;
        g_Wol[tap][o][c] = l;
    }
}

// ------------------------------ K2: NCHW -> NHWC (+ hi/lo split) -------------
__global__ void k2_transpose(const float* __restrict__ u,
                             const float* __restrict__ v) {
    __shared__ float tile[32][33];
    int img = blockIdx.z;
    int t = img >> 1, b = img & 1;
    const float* x = t ? v : u;
    int n0 = blockIdx.x * 32, c0 = blockIdx.y * 32;
    int tx = threadIdx.x, ty = threadIdx.y;
#pragma unroll
    for (int i = 0; i < 32; i += 8)
        tile[ty + i][tx] = x[(size_t)(b * Cc + c0 + ty + i) * Nn + n0 + tx];
    __syncthreads();
#pragma unroll
    for (int i = 0; i < 32; i += 8) {
        float vv = tile[tx][ty + i];
        int n = n0 + ty + i, c = c0 + tx;
        g_xnhwc[img][n][c] = vv;
        __half h = __float2half_rn(vv);
        g_xh[img][n][c] = h;
        g_xl[img][n][c] = __float2half_rn(vv - __half2float(h));
    }
}

// ------------------------------ K1: offset conv via mma fp16x3 ---------------
// Block = one image row (128 px) x 32 outs (18 real), 256 threads (8 warps,
// m16 each). Interior slots are fully overwritten by cp.async each chunk, so
// zeroing happens ONCE for halo slots (0,129) and OOB rows only.
#define XP 80                       // bytes per 32-ch half row (64 data + 16 pad)
#define XHALF (3 * 130 * XP)        // 31200
#define OFF_XL  XHALF
#define OFF_WH  (2 * XHALF)         // 62400
#define WHALF (KK9 * 32 * XP)       // 23040
#define OFF_WL  (OFF_WH + WHALF)
#define K1_DYN  (OFF_WH + 2 * WHALF)  // 108480

__global__ void __launch_bounds__(256, 2) k1_offset(const float* __restrict__ offset_b) {
    extern __shared__ char S[];
    uint32_t sb = smem_u32(S);
    int t = threadIdx.x, lane = t & 31, wid = t >> 5;
    int y = blockIdx.x, img = blockIdx.y;

    float acc[4][4];
#pragma unroll
    for (int nt = 0; nt < 4; nt++)
#pragma unroll
        for (int f = 0; f < 4; f++) acc[nt][f] = 0.f;

    // ---- one-time zeroing: halo slots + OOB rows (both halves) ----
    if (t < 12) {
        int half = (t >= 6) ? 1 : 0;
        int k = t - half * 6;
        int r3 = k >> 1;
        int sl = (k & 1) ? 129 : 0;
        char* p = S + half * XHALF + (r3 * 130 + sl) * XP;
#pragma unroll
        for (int b2 = 0; b2 < XP; b2 += 16)
            *(float4*)(p + b2) = make_float4(0.f, 0.f, 0.f, 0.f);
    }
#pragma unroll
    for (int r3 = 0; r3 < 3; r3++) {
        int gy = y + r3 - 1;
        if ((unsigned)gy >= (unsigned)Hh) {
            for (int i = t * 16; i < 130 * XP; i += 256 * 16) {
                *(float4*)(S + r3 * 130 * XP + i) = make_float4(0.f, 0.f, 0.f, 0.f);
                *(float4*)(S + XHALF + r3 * 130 * XP + i) = make_float4(0.f, 0.f, 0.f, 0.f);
            }
        }
    }

    uint32_t arow = (lane & 7) + ((lane >> 3) & 1) * 8;
    uint32_t acolB = ((lane >> 4) & 1) * 16;
    uint32_t brow = (lane & 7) + ((lane >> 4) & 1) * 8;
    uint32_t bcolB = ((lane >> 3) & 1) * 16;
    int wm = wid;                    // 8 warps x m16 = 128 px

    for (int ch = 0; ch < 4; ch++) {
        __syncthreads();             // prev chunk mma done (and initial zero visible)
        // x rows: 3 rows x 128 px x 4 chunks x 2 halves = 3072 cp chunks
#pragma unroll
        for (int j = 0; j < 12; j++) {
            int idx = t + 256 * j;
            int sel = (idx >= 1536) ? 1 : 0;
            int i2 = idx - sel * 1536;
            int row3 = i2 >> 9;
            int win = i2 & 511;
            int px = win >> 2, c16 = win & 3;
            int gy = y + row3 - 1;
            if ((unsigned)gy < (unsigned)Hh) {
                const __half* gsrc = sel ? &g_xl[img][gy * Ww + px][ch * 32 + c16 * 8]
                                         : &g_xh[img][gy * Ww + px][ch * 32 + c16 * 8];
                cp16(sb + sel * XHALF + ((row3 * 130) + px + 1) * XP + c16 * 16, gsrc);
            }
        }
#pragma unroll
        for (int j = 0; j < 9; j++) {
            int idx = t + 256 * j;
            int sel = (idx >= 1152) ? 1 : 0;
            int i2 = idx - sel * 1152;
            int tap = i2 >> 7;
            int win = i2 & 127;
            int o = win >> 2, c16 = win & 3;
            const __half* gsrc = sel ? &g_Wol[tap][o][ch * 32 + c16 * 8]
                                     : &g_Woh[tap][o][ch * 32 + c16 * 8];
            cp16(sb + OFF_WH + sel * WHALF + (tap * 32 + o) * XP + c16 * 16, gsrc);
        }
        asm volatile("cp.async.commit_group;" ::: "memory");
        asm volatile("cp.async.wait_group 0;" ::: "memory");
        __syncthreads();

#pragma unroll
        for (int tap = 0; tap < KK9; tap++) {
            int di = tap / 3, dj = tap % 3;
            uint32_t abase = sb + ((uint32_t)(di * 130 + dj + wm * 16) + arow) * XP + acolB;
            uint32_t bbase = sb + OFF_WH + (tap * 32 + brow) * XP + bcolB;
#pragma unroll
            for (int ks = 0; ks < 2; ks++) {
                uint32_t kB = ks * 32;
                uint32_t ah[4], al[4], bh[2][4], bl[2][4];
                ldm4(ah, abase + kB);
                ldm4(al, abase + XHALF + kB);
                ldm4(bh[0], bbase + kB);
                ldm4(bh[1], bbase + 16 * XP + kB);
                ldm4(bl[0], bbase + WHALF + kB);
                ldm4(bl[1], bbase + WHALF + 16 * XP + kB);
#pragma unroll
                for (int ntq = 0; ntq < 2; ntq++) {
#pragma unroll
                    for (int sub = 0; sub < 2; sub++) {
                        int nt = ntq * 2 + sub;
                        uint32_t b0h = bh[ntq][sub * 2], b1h = bh[ntq][sub * 2 + 1];
                        uint32_t b0l = bl[ntq][sub * 2], b1l = bl[ntq][sub * 2 + 1];
                        mma16816(acc[nt], ah[0], ah[1], ah[2], ah[3], b0h, b1h);
                        mma16816(acc[nt], al[0], al[1], al[2], al[3], b0h, b1h);
                        mma16816(acc[nt], ah[0], ah[1], ah[2], ah[3], b0l, b1l);
                    }
                }
            }
        }
    }

    int px0 = wm * 16 + (lane >> 2);
    int nbase = y * Ww;
#pragma unroll
    for (int nt = 0; nt < 4; nt++) {
        int col = nt * 8 + (lane & 3) * 2;
        if (col < OCH) {
            float b0 = offset_b[col], b1 = offset_b[col + 1];
            g_off[img][nbase + px0][col]     = acc[nt][0] + b0;
            g_off[img][nbase + px0][col + 1] = acc[nt][1] + b1;
            g_off[img][nbase + px0 + 8][col]     = acc[nt][2] + b0;
            g_off[img][nbase + px0 + 8][col + 1] = acc[nt][3] + b1;
        }
    }
}

// ------------------------------ K3: deformable conv via mma.sync fp16x3 ------
// Block: 64 px x 128 co, 256 threads (8 warps = 4 m16 x 2 n64), 2 blocks/SM.
#define PA 68                       // u32 row pitch (272 bytes)
#define MATB (128 * PA * 4)         // 34816 bytes (B half-matrix)
#define MATA (64 * PA * 4)          // 17408 bytes (A half-matrix)
#define OFF_ALO  MATA
#define OFF_BHI  (2 * MATA)
#define OFF_BLO  (2 * MATA + MATB)
#define OFF_OFS  (2 * MATA + 2 * MATB)          // int4[64]
#define OFF_WTS  (2 * MATA + 2 * MATB + 1024)   // float4[64]
#define K3_DYN   (2 * MATA + 2 * MATB + 2048)   // 106496

__device__ __forceinline__ void prefetch_B(uint32_t sb, int kk, int t) {
    uint32_t base = sb + OFF_BHI;
#pragma unroll
    for (int j = 0; j < 16; j++) {
        int chunk = t + 256 * j;              // 0..4095
        int lo = chunk >> 11;                 // 0: hi, 1: lo (2048 each: exact)
        int cc = chunk & 2047;
        int row = cc >> 4, ch16 = cc & 15;
        const __half* gsrc = lo ? &g_Wl[kk][row][ch16 * 8] : &g_Wh[kk][row][ch16 * 8];
        cp16(base + lo * MATB + (row * PA + ch16 * 4) * 4, gsrc);
    }
    asm volatile("cp.async.commit_group;" ::: "memory");
}

__global__ void __launch_bounds__(256, 2) k3_deform(const float* __restrict__ dcn_b) {
    extern __shared__ char B[];
    uint32_t sb = smem_u32(B);
    uint32_t* A32h = (uint32_t*)B;
    uint32_t* A32l = (uint32_t*)(B + OFF_ALO);
    int4*   s_ofs = (int4*)(B + OFF_OFS);
    float4* s_w   = (float4*)(B + OFF_WTS);

    int t = threadIdx.x, lane = t & 31, wid = t >> 5;
    int img = blockIdx.y, n0 = blockIdx.x * 64;
    const float* X = &g_xnhwc[img][0][0];

    float acc[8][4];
#pragma unroll
    for (int nt = 0; nt < 8; nt++)
#pragma unroll
        for (int f = 0; f < 4; f++) acc[nt][f] = 0.f;

    int cq = t & 31, pxg = t >> 5;
    int c = cq * 4;
    int wm = wid & 3, wn = wid >> 2;

    uint32_t arow = (lane & 7) + ((lane >> 3) & 1) * 8;
    uint32_t acolB = ((lane >> 4) & 1) * 16;
    uint32_t aAddr0 = sb + (wm * 16 + arow) * 272 + acolB;
    uint32_t brow = (lane & 7) + ((lane >> 4) & 1) * 8;
    uint32_t bcolB = ((lane >> 3) & 1) * 16;
    uint32_t bOff = (wn * 64 + brow) * 272 + bcolB;

    for (int kk = 0; kk < KK9; kk++) {
        __syncthreads();
        prefetch_B(sb, kk, t);

        if (t < 64) {
            int n = n0 + t;
            float dy = g_off[img][n][kk * 2 + 0];
            float dx = g_off[img][n][kk * 2 + 1];
            float py  = (float)((n >> 7) + kk / 3 - 1) + dy;
            float pxf = (float)((n & 127) + kk % 3 - 1) + dx;
            float y0f = floorf(py), x0f = floorf(pxf);
            int y0 = (int)y0f, x0 = (int)x0f;
            float wy = py - y0f, wx = pxf - x0f;
            int y1 = y0 + 1, x1 = x0 + 1;
            bool vy0 = (unsigned)y0 < (unsigned)Hh, vy1 = (unsigned)y1 < (unsigned)Hh;
            bool vx0 = (unsigned)x0 < (unsigned)Ww, vx1 = (unsigned)x1 < (unsigned)Ww;
            int yc0 = min(max(y0, 0), Hh - 1), yc1 = min(max(y1, 0), Hh - 1);
            int xc0 = min(max(x0, 0), Ww - 1), xc1 = min(max(x1, 0), Ww - 1);
            s_ofs[t] = make_int4((yc0 * Ww + xc0) * Cc, (yc0 * Ww + xc1) * Cc,
                                 (yc1 * Ww + xc0) * Cc, (yc1 * Ww + xc1) * Cc);
            s_w[t] = make_float4(vy0 && vx0 ? (1.f - wy) * (1.f - wx) : 0.f,
                                 vy0 && vx1 ? (1.f - wy) * wx : 0.f,
                                 vy1 && vx0 ? wy * (1.f - wx) : 0.f,
                                 vy1 && vx1 ? wy * wx : 0.f);
        }
        __syncthreads();

#pragma unroll 4
        for (int i = 0; i < 8; i++) {
            int px = pxg + i * 8;
            int4  o = s_ofs[px];
            float4 w = s_w[px];
            float4 v0 = *(const float4*)(X + o.x + c);
            float4 v1 = *(const float4*)(X + o.y + c);
            float4 v2 = *(const float4*)(X + o.z + c);
            float4 v3 = *(const float4*)(X + o.w + c);
            float s0 = w.x * v0.x + w.y * v1.x + w.z * v2.x + w.w * v3.x;
            float s1 = w.x * v0.y + w.y * v1.y + w.z * v2.y + w.w * v3.y;
            float s2 = w.x * v0.z + w.y * v1.z + w.z * v2.z + w.w * v3.z;
            float s3 = w.x * v0.w + w.y * v1.w + w.z * v2.w + w.w * v3.w;
            half2 h01 = __floats2half2_rn(s0, s1);
            half2 h23 = __floats2half2_rn(s2, s3);
            float2 f01 = __half22float2(h01), f23 = __half22float2(h23);
            half2 l01 = __floats2half2_rn(s0 - f01.x, s1 - f01.y);
            half2 l23 = __floats2half2_rn(s2 - f23.x, s3 - f23.y);
            *(uint2*)&A32h[px * PA + cq * 2] =
                make_uint2(*(uint32_t*)&h01, *(uint32_t*)&h23);
            *(uint2*)&A32l[px * PA + cq * 2] =
                make_uint2(*(uint32_t*)&l01, *(uint32_t*)&l23);
        }
        asm volatile("cp.async.wait_group 0;" ::: "memory");
        __syncthreads();

        uint32_t bh_base = sb + OFF_BHI + bOff;
        uint32_t bl_base = sb + OFF_BLO + bOff;

#pragma unroll
        for (int kt = 0; kt < 8; kt++) {
            uint32_t kB = kt * 32;
            uint32_t ah[4], al[4], bh[4][4], bl[4][4];
            ldm4(ah, aAddr0 + kB);
            ldm4(al, aAddr0 + OFF_ALO + kB);
#pragma unroll
            for (int ntq = 0; ntq < 4; ntq++) {
                ldm4(bh[ntq], bh_base + ntq * 16 * 272 + kB);
                ldm4(bl[ntq], bl_base + ntq * 16 * 272 + kB);
            }
#pragma unroll
            for (int ntq = 0; ntq < 4; ntq++) {
#pragma unroll
                for (int sub = 0; sub < 2; sub++) {
                    int nt = ntq * 2 + sub;
                    uint32_t b0h = bh[ntq][sub * 2], b1h = bh[ntq][sub * 2 + 1];
                    uint32_t b0l = bl[ntq][sub * 2], b1l = bl[ntq][sub * 2 + 1];
                    mma16816(acc[nt], ah[0], ah[1], ah[2], ah[3], b0h, b1h);
                    mma16816(acc[nt], al[0], al[1], al[2], al[3], b0h, b1h);
                    mma16816(acc[nt], ah[0], ah[1], ah[2], ah[3], b0l, b1l);
                }
            }
        }
    }

    int r0 = wm * 16 + (lane >> 2);
#pragma unroll
    for (int nt = 0; nt < 8; nt++) {
        int col = wn * 64 + nt * 8 + (lane & 3) * 2;
        float2 bias = *(const float2*)(dcn_b + col);
        float2 o0 = make_float2(acc[nt][0] + bias.x, acc[nt][1] + bias.y);
        float2 o1 = make_float2(acc[nt][2] + bias.x, acc[nt][3] + bias.y);
        *(float2*)&g_xd[img][n0 + r0][col] = o0;
        *(float2*)&g_xd[img][n0 + r0 + 8][col] = o1;
    }
}

// ------------------------------ K4: Gram partials G = Ud^T Vd ----------------
// 256-row chunks (8 x 32-row subtiles), 64 chunks per batch.
__global__ void k4_gpart() {
    __shared__ float Us[32][129];
    __shared__ float Vs[32][129];
    int b = blockIdx.y, chunk = blockIdx.x;
    int n0 = chunk * 256, t = threadIdx.x;
    int il = t & 15, jl = t >> 4;

    float acc[8][8];
#pragma unroll
    for (int ii = 0; ii < 8; ii++)
#pragma unroll
        for (int jj = 0; jj < 8; jj++) acc[ii][jj] = 0.f;
    float colsum = 0.f;

    for (int s = 0; s < 8; s++) {
        __syncthreads();
        for (int idx = t; idx < 32 * 128; idx += 256) {
            int cc = idx & 127, nl = idx >> 7;
            Us[nl][cc] = g_xd[b][n0 + s * 32 + nl][cc];
            Vs[nl][cc] = g_xd[2 + b][n0 + s * 32 + nl][cc];
        }
        __syncthreads();
#pragma unroll 4
        for (int nl = 0; nl < 32; nl++) {
            float av[8], bv[8];
#pragma unroll
            for (int ii = 0; ii < 8; ii++) av[ii] = Us[nl][il + 16 * ii];
#pragma unroll
            for (int jj = 0; jj < 8; jj++) bv[jj] = Vs[nl][jl + 16 * jj];
#pragma unroll
            for (int ii = 0; ii < 8; ii++)
#pragma unroll
                for (int jj = 0; jj < 8; jj++) acc[ii][jj] += av[ii] * bv[jj];
        }
        if (t < 128) {
            for (int nl = 0; nl < 32; nl++) colsum += Us[nl][t];
        } else {
            int cc = t - 128;
            for (int nl = 0; nl < 32; nl++) colsum += Vs[nl][cc];
        }
    }
    if (t < 128) g_sup[b][chunk][t] = colsum;
    else         g_svp[b][chunk][t - 128] = colsum;

    for (int g = 0; g < 4; g++) {
        __syncthreads();
#pragma unroll
        for (int jj = 0; jj < 8; jj++) {
            Us[il][jl + 16 * jj]      = acc[2 * g][jj];
            Us[16 + il][jl + 16 * jj] = acc[2 * g + 1][jj];
        }
        __syncthreads();
        for (int idx = t; idx < 32 * 128; idx += 256) {
            int j = idx & 127, r = idx >> 7;
            g_Gp[b][chunk][(32 * g + r) * 128 + j] = Us[r][j];
        }
    }
}

// ------------------------------ K4b: reduce partials -------------------------
__global__ void k4b_reduce() {
    int idx = blockIdx.x * 256 + threadIdx.x;
    if (idx < Bb * Cc * Cc) {
        int b = idx >> 14;
        int rem = idx & (Cc * Cc - 1);
        float s = 0.f;
        for (int ch = 0; ch < NCHUNK; ch++) s += g_Gp[b][ch][rem];
        g_G[b][rem] = s;
    } else {
        int k = idx - Bb * Cc * Cc;
        if (k < 2 * Bb * Cc) {
            int sel = k >> 8;
            int b = (k >> 7) & 1;
            int c = k & 127;
            float s = 0.f;
            if (sel) { for (int ch = 0; ch < NCHUNK; ch++) s += g_svp[b][ch][c]; g_sv[b][c] = s; }
            else     { for (int ch = 0; ch < NCHUNK; ch++) s += g_sup[b][ch][c]; g_su[b][c] = s; }
        }
    }
}

// ------------------------------ K5: tiny attention math ----------------------
__global__ void k5_attn(const float* __restrict__ q_w, const float* __restrict__ q_b,
                        const float* __restrict__ k_w, const float* __restrict__ k_b,
                        const float* __restrict__ v_w, const float* __restrict__ v_b) {
    __shared__ float P[4][128];
    __shared__ float L[4][128];
    __shared__ float ksv[128];
    __shared__ float qsu[4];
    int b = blockIdx.y;
    int i0 = blockIdx.x * 4;
    int t = threadIdx.x;
    int lane = t & 31, wid = t >> 5;

    if (t < 128) {
        float s = 0.f;
        for (int a = 0; a < 128; a++) s += k_w[t * 128 + a] * g_sv[b][a];
        ksv[t] = s;
    } else if (t < 132) {
        int i = i0 + (t - 128);
        float s = 0.f;
        for (int a = 0; a < 128; a++) s += q_w[i * 128 + a] * g_su[b][a];
        qsu[t - 128] = s;
    }
    __syncthreads();

    for (int idx = t; idx < 4 * 128; idx += 256) {
        int a = idx & 127, ii = idx >> 7;
        int i = i0 + ii;
        float s = 0.f;
        for (int m = 0; m < 128; m++) s += q_w[i * 128 + m] * g_G[b][m * 128 + a];
        P[ii][a] = s;
    }
    __syncthreads();

    const float scale = 0.088388347648318447f; // 128^-0.5
    for (int idx = t; idx < 4 * 128; idx += 256) {
        int j = idx & 127, ii = idx >> 7;
        int i = i0 + ii;
        float s = 0.f;
        for (int a = 0; a < 128; a++) s += P[ii][a] * k_w[j * 128 + a];
        s += qsu[ii] * k_b[j] + q_b[i] * ksv[j] + (float)Nn * q_b[i] * k_b[j];
        L[ii][j] = s * scale;
    }
    __syncthreads();

    if (wid < 4) {
        int r = wid;
        float v[4];
        float m = -1e30f;
#pragma unroll
        for (int q = 0; q < 4; q++) { v[q] = L[r][lane + 32 * q]; m = fmaxf(m, v[q]); }
#pragma unroll
        for (int o = 16; o > 0; o >>= 1) m = fmaxf(m, __shfl_xor_sync(0xFFFFFFFFu, m, o));
        float s = 0.f;
#pragma unroll
        for (int q = 0; q < 4; q++) { v[q] = expf(v[q] - m); s += v[q]; }
#pragma unroll
        for (int o = 16; o > 0; o >>= 1) s += __shfl_xor_sync(0xFFFFFFFFu, s, o);
        float inv = 1.f / s;
#pragma unroll
        for (int q = 0; q < 4; q++) L[r][lane + 32 * q] = v[q] * inv;
    }
    __syncthreads();

    for (int idx = t; idx < 4 * 128; idx += 256) {
        int m = idx & 127, ii = idx >> 7;
        float s = 0.f;
        for (int j = 0; j < 128; j++) s += L[ii][j] * v_w[j * 128 + m];
        g_Mt[b][m * 128 + (i0 + ii)] = s;
    }
    if (t < 4) {
        float s = 0.f;
        for (int j = 0; j < 128; j++) s += L[t][j] * v_b[j];
        g_r[b][i0 + t] = s;
    }
}

// ------------------------------ K6: out = M @ Vd^T + r -----------------------
__global__ void k6_out(float* __restrict__ out) {
    __shared__ float Ms[32][129];
    __shared__ float Vs[32][129];
    int b = blockIdx.y, n0 = blockIdx.x * 128, t = threadIdx.x;
    int il = t & 15, jl = t >> 4;

    float acc[8][8];
#pragma unroll
    for (int ii = 0; ii < 8; ii++)
#pragma unroll
        for (int jj = 0; jj < 8; jj++) acc[ii][jj] = 0.f;

    for (int s = 0; s < 4; s++) {
        __syncthreads();
        for (int idx = t; idx < 32 * 128; idx += 256) {
            int i = idx & 127, mm = idx >> 7;
            Ms[mm][i] = g_Mt[b][(s * 32 + mm) * 128 + i];
        }
        for (int idx = t; idx < 32 * 128; idx += 256) {
            int mmr = idx & 31, nl = idx >> 5;
            Vs[mmr][nl] = g_xd[2 + b][n0 + nl][s * 32 + mmr];
        }
        __syncthreads();
#pragma unroll 4
        for (int mm = 0; mm < 32; mm++) {
            float av[8], bv[8];
#pragma unroll
            for (int ii = 0; ii < 8; ii++) av[ii] = Ms[mm][il + 16 * ii];
#pragma unroll
            for (int jj = 0; jj < 8; jj++) bv[jj] = Vs[mm][jl + 16 * jj];
#pragma unroll
            for (int ii = 0; ii < 8; ii++)
#pragma unroll
                for (int jj = 0; jj < 8; jj++) acc[ii][jj] += av[ii] * bv[jj];
        }
    }

    for (int g = 0; g < 4; g++) {
        __syncthreads();
#pragma unroll
        for (int jj = 0; jj < 8; jj++) {
            Ms[il][jl + 16 * jj]      = acc[2 * g][jj];
            Ms[16 + il][jl + 16 * jj] = acc[2 * g + 1][jj];
        }
        __syncthreads();
        for (int idx = t; idx < 32 * 128; idx += 256) {
            int j = idx & 127, r = idx >> 7;
            int i = 32 * g + r;
            out[(size_t)(b * Cc + i) * Nn + n0 + j] = Ms[r][j] + g_r[b][i];
        }
    }
}

// ------------------------------ launch ---------------------------------------
extern "C" void kernel_launch(void* const* d_in, const int* in_sizes, int n_in,
                              void* d_out, int out_size) {
    (void)in_sizes; (void)n_in; (void)out_size;
    const float* u        = (const float*)d_in[0];
    const float* v        = (const float*)d_in[1];
    const float* offset_w = (const float*)d_in[2];
    const float* offset_b = (const float*)d_in[3];
    const float* dcn_w    = (const float*)d_in[4];
    const float* dcn_b    = (const float*)d_in[5];
    const float* q_w      = (const float*)d_in[6];
    const float* q_b      = (const float*)d_in[7];
    const float* k_w      = (const float*)d_in[8];
    const float* k_b      = (const float*)d_in[9];
    const float* v_w      = (const float*)d_in[10];
    const float* v_b      = (const float*)d_in[11];
    float* out = (float*)d_out;

    cudaFuncSetAttribute(k1_offset, cudaFuncAttributeMaxDynamicSharedMemorySize, K1_DYN);
    cudaFuncSetAttribute(k3_deform, cudaFuncAttributeMaxDynamicSharedMemorySize, K3_DYN);

    k0_prep<<<(KK9 * Cc * Cc + 255) / 256, 256>>>(dcn_w, offset_w);
    k2_transpose<<<dim3(Nn / 32, Cc / 32, NIMG), dim3(32, 8)>>>(u, v);
    k1_offset<<<dim3(Hh, NIMG), 256, K1_DYN>>>(offset_b);
    k3_deform<<<dim3(Nn / 64, NIMG), 256, K3_DYN>>>(dcn_b);
    k4_gpart<<<dim3(NCHUNK, Bb), 256>>>();
    k4b_reduce<<<130, 256>>>();
    k5_attn<<<dim3(32, Bb), 256>>>(q_w, q_b, k_w, k_b, v_w, v_b);
    k6_out<<<dim3(Nn / 128, Bb), 256>>>(out);
}

// round 13
// speedup vs baseline: 1.0705x; 1.0705x over previous
#include <cuda_runtime.h>
#include <cuda_fp16.h>
#include <math.h>
#include <stdint.h>

#define Hh 128
#define Ww 128
#define Cc 128
#define Nn (Hh*Ww)
#define Bb 2
#define NIMG 4          // img = tensor*2 + batch ; tensor 0 = u, 1 = v
#define KK9 9
#define OCH 18
#define NCHUNK 128

// -------- scratch (static device allocations; no runtime alloc allowed) ------
__device__ float g_xnhwc[NIMG][Nn][Cc];   // inputs transposed to NHWC (fp32)
__device__ __half g_xh[NIMG][Nn][Cc];     // x hi-half
__device__ __half g_xl[NIMG][Nn][Cc];     // x lo-half
__device__ float g_off[NIMG][Nn][OCH];    // offset conv output, per-pixel 18 vals
__device__ float g_xd[NIMG][Nn][Cc];      // deformable conv outputs (NHWC)
__device__ __half g_Wh[KK9][Cc][Cc];      // dcn_w hi-half [kk][co][c]
__device__ __half g_Wl[KK9][Cc][Cc];      // dcn_w lo-half
__device__ __half g_Woh[KK9][32][Cc];     // offset_w hi [tap][out(pad32)][c]
__device__ __half g_Wol[KK9][32][Cc];     // offset_w lo
__device__ float g_Gp[Bb][NCHUNK][Cc*Cc]; // Gram partials
__device__ float g_sup[Bb][NCHUNK][Cc];
__device__ float g_svp[Bb][NCHUNK][Cc];
__device__ float g_G[Bb][Cc*Cc];
__device__ float g_su[Bb][Cc];
__device__ float g_sv[Bb][Cc];
__device__ float g_Mt[Bb][Cc*Cc];         // (attn @ Vw)^T  [m][i]
__device__ float g_r[Bb][Cc];             // attn @ vb

// ------------------------------ common helpers -------------------------------
__device__ __forceinline__ void mma16816(float* d, uint32_t a0, uint32_t a1,
                                         uint32_t a2, uint32_t a3,
                                         uint32_t b0, uint32_t b1) {
    asm volatile(
        "mma.sync.aligned.m16n8k16.row.col.f32.f16.f16.f32 "
        "{%0,%1,%2,%3}, {%4,%5,%6,%7}, {%8,%9}, {%0,%1,%2,%3};"
        : "+f"(d[0]), "+f"(d[1]), "+f"(d[2]), "+f"(d[3])
        : "r"(a0), "r"(a1), "r"(a2), "r"(a3), "r"(b0), "r"(b1));
}
__device__ __forceinline__ uint32_t smem_u32(const void* p) {
    uint32_t a;
    asm("{ .reg .u64 t; cvta.to.shared.u64 t, %1; cvt.u32.u64 %0, t; }" : "=r"(a) : "l"(p));
    return a;
}
__device__ __forceinline__ void ldm4(uint32_t* r, uint32_t addr) {
    asm volatile("ldmatrix.sync.aligned.m8n8.x4.shared.b16 {%0,%1,%2,%3}, [%4];"
                 : "=r"(r[0]), "=r"(r[1]), "=r"(r[2]), "=r"(r[3]) : "r"(addr));
}
__device__ __forceinline__ void cp16(uint32_t s, const void* g) {
    asm volatile("cp.async.cg.shared.global [%0], [%1], 16;" :: "r"(s), "l"(g));
}

// ------------------------------ K0: weight prep ------------------------------
__global__ void k0_prep(const float* __restrict__ dcn_w,
                        const float* __restrict__ offset_w) {
    int idx = blockIdx.x * blockDim.x + threadIdx.x;
    if (idx < KK9 * Cc * Cc) {
        int kk = idx / (Cc * Cc);
        int rem = idx % (Cc * Cc);
        int co = rem >> 7, c = rem & 127;
        float w = dcn_w[(co * Cc + c) * KK9 + kk];
        __half h = __float2half_rn(w);
        __half l = __float2half_rn(w - __half2float(h));
        g_Wh[kk][co][c] = h;
        g_Wl[kk][co][c] = l;
    }
    if (idx < KK9 * 32 * Cc) {
        int tap = idx / (32 * Cc);
        int rem = idx % (32 * Cc);
        int o = rem >> 7, c = rem & 127;
        float w = (o < OCH) ? offset_w[(o * Cc + c) * KK9 + tap] : 0.f;
        __half h = __float2half_rn(w);
        __half l = __float2half_rn(w - __half2float(h));
        g_Woh[tap][o][c] = h;
        g_Wol[tap][o][c] = l;
    }
}

// ------------------------------ K2: NCHW -> NHWC (+ hi/lo split) -------------
__global__ void k2_transpose(const float* __restrict__ u,
                             const float* __restrict__ v) {
    __shared__ float tile[32][33];
    int img = blockIdx.z;
    int t = img >> 1, b = img & 1;
    const float* x = t ? v : u;
    int n0 = blockIdx.x * 32, c0 = blockIdx.y * 32;
    int tx = threadIdx.x, ty = threadIdx.y;
#pragma unroll
    for (int i = 0; i < 32; i += 8)
        tile[ty + i][tx] = x[(size_t)(b * Cc + c0 + ty + i) * Nn + n0 + tx];
    __syncthreads();
#pragma unroll
    for (int i = 0; i < 32; i += 8) {
        float vv = tile[tx][ty + i];
        int n = n0 + ty + i, c = c0 + tx;
        g_xnhwc[img][n][c] = vv;
        __half h = __float2half_rn(vv);
        g_xh[img][n][c] = h;
        g_xl[img][n][c] = __float2half_rn(vv - __half2float(h));
    }
}

// ------------------------------ K1: offset conv via mma fp16x3 ---------------
#define XP 80                       // bytes per 32-ch half row (64 data + 16 pad)
#define XHALF (3 * 130 * XP)        // 31200
#define OFF_XL  XHALF
#define OFF_WH  (2 * XHALF)         // 62400
#define WHALF (KK9 * 32 * XP)       // 23040
#define OFF_WL  (OFF_WH + WHALF)
#define K1_DYN  (OFF_WH + 2 * WHALF)  // 108480

__global__ void __launch_bounds__(256, 2) k1_offset(const float* __restrict__ offset_b) {
    extern __shared__ char S[];
    uint32_t sb = smem_u32(S);
    int t = threadIdx.x, lane = t & 31, wid = t >> 5;
    int y = blockIdx.x, img = blockIdx.y;

    float acc[4][4];
#pragma unroll
    for (int nt = 0; nt < 4; nt++)
#pragma unroll
        for (int f = 0; f < 4; f++) acc[nt][f] = 0.f;

    uint32_t arow = (lane & 7) + ((lane >> 3) & 1) * 8;
    uint32_t acolB = ((lane >> 4) & 1) * 16;
    uint32_t brow = (lane & 7) + ((lane >> 4) & 1) * 8;
    uint32_t bcolB = ((lane >> 3) & 1) * 16;
    int wm = wid;                    // 8 warps x m16 = 128 px

    for (int ch = 0; ch < 4; ch++) {
        __syncthreads();             // prev chunk mma done
        for (int i = t * 16; i < 2 * XHALF; i += 256 * 16)
            *(float4*)(S + i) = make_float4(0.f, 0.f, 0.f, 0.f);
        __syncthreads();
        // x rows: hi chunks [0,1536), lo [1536,3072)
#pragma unroll
        for (int j = 0; j < 12; j++) {
            int idx = t + 256 * j;
            int sel = (idx >= 1536) ? 1 : 0;
            int i2 = idx - sel * 1536;
            int row3 = i2 >> 9;
            int win = i2 & 511;
            int px = win >> 2, c16 = win & 3;
            int gy = y + row3 - 1;
            if ((unsigned)gy < (unsigned)Hh) {
                const __half* gsrc = sel ? &g_xl[img][gy * Ww + px][ch * 32 + c16 * 8]
                                         : &g_xh[img][gy * Ww + px][ch * 32 + c16 * 8];
                cp16(sb + sel * XHALF + ((row3 * 130) + px + 1) * XP + c16 * 16, gsrc);
            }
        }
#pragma unroll
        for (int j = 0; j < 9; j++) {
            int idx = t + 256 * j;
            int sel = (idx >= 1152) ? 1 : 0;
            int i2 = idx - sel * 1152;
            int tap = i2 >> 7;
            int win = i2 & 127;
            int o = win >> 2, c16 = win & 3;
            const __half* gsrc = sel ? &g_Wol[tap][o][ch * 32 + c16 * 8]
                                     : &g_Woh[tap][o][ch * 32 + c16 * 8];
            cp16(sb + OFF_WH + sel * WHALF + (tap * 32 + o) * XP + c16 * 16, gsrc);
        }
        asm volatile("cp.async.commit_group;" ::: "memory");
        asm volatile("cp.async.wait_group 0;" ::: "memory");
        __syncthreads();

#pragma unroll
        for (int tap = 0; tap < KK9; tap++) {
            int di = tap / 3, dj = tap % 3;
            uint32_t abase = sb + ((uint32_t)(di * 130 + dj + wm * 16) + arow) * XP + acolB;
            uint32_t bbase = sb + OFF_WH + (tap * 32 + brow) * XP + bcolB;
#pragma unroll
            for (int ks = 0; ks < 2; ks++) {
                uint32_t kB = ks * 32;
                uint32_t ah[4], al[4], bh[2][4], bl[2][4];
                ldm4(ah, abase + kB);
                ldm4(al, abase + XHALF + kB);
                ldm4(bh[0], bbase + kB);
                ldm4(bh[1], bbase + 16 * XP + kB);
                ldm4(bl[0], bbase + WHALF + kB);
                ldm4(bl[1], bbase + WHALF + 16 * XP + kB);
#pragma unroll
                for (int ntq = 0; ntq < 2; ntq++) {
#pragma unroll
                    for (int sub = 0; sub < 2; sub++) {
                        int nt = ntq * 2 + sub;
                        uint32_t b0h = bh[ntq][sub * 2], b1h = bh[ntq][sub * 2 + 1];
                        uint32_t b0l = bl[ntq][sub * 2], b1l = bl[ntq][sub * 2 + 1];
                        mma16816(acc[nt], ah[0], ah[1], ah[2], ah[3], b0h, b1h);
                        mma16816(acc[nt], al[0], al[1], al[2], al[3], b0h, b1h);
                        mma16816(acc[nt], ah[0], ah[1], ah[2], ah[3], b0l, b1l);
                    }
                }
            }
        }
    }

    int px0 = wm * 16 + (lane >> 2);
    int nbase = y * Ww;
#pragma unroll
    for (int nt = 0; nt < 4; nt++) {
        int col = nt * 8 + (lane & 3) * 2;
        if (col < OCH) {
            float b0 = offset_b[col], b1 = offset_b[col + 1];
            g_off[img][nbase + px0][col]     = acc[nt][0] + b0;
            g_off[img][nbase + px0][col + 1] = acc[nt][1] + b1;
            g_off[img][nbase + px0 + 8][col]     = acc[nt][2] + b0;
            g_off[img][nbase + px0 + 8][col + 1] = acc[nt][3] + b1;
        }
    }
}

// ------------------------------ K3: deformable conv via mma.sync fp16x3 ------
// Block: 64 px x 128 co, 256 threads (8 warps = 4 m16 x 2 n64), 2 blocks/SM.
#define PA 68                       // u32 row pitch (272 bytes)
#define MATB (128 * PA * 4)         // 34816 bytes (B half-matrix)
#define MATA (64 * PA * 4)          // 17408 bytes (A half-matrix)
#define OFF_ALO  MATA
#define OFF_BHI  (2 * MATA)
#define OFF_BLO  (2 * MATA + MATB)
#define OFF_OFS  (2 * MATA + 2 * MATB)          // int4[64]
#define OFF_WTS  (2 * MATA + 2 * MATB + 1024)   // float4[64]
#define K3_DYN   (2 * MATA + 2 * MATB + 2048)   // 106496

__device__ __forceinline__ void prefetch_B(uint32_t sb, int kk, int t) {
    uint32_t base = sb + OFF_BHI;
#pragma unroll
    for (int j = 0; j < 16; j++) {
        int chunk = t + 256 * j;              // 0..4095
        int lo = chunk >> 11;                 // 0: hi, 1: lo (2048 each: exact)
        int cc = chunk & 2047;
        int row = cc >> 4, ch16 = cc & 15;
        const __half* gsrc = lo ? &g_Wl[kk][row][ch16 * 8] : &g_Wh[kk][row][ch16 * 8];
        cp16(base + lo * MATB + (row * PA + ch16 * 4) * 4, gsrc);
    }
    asm volatile("cp.async.commit_group;" ::: "memory");
}

__global__ void __launch_bounds__(256, 2) k3_deform(const float* __restrict__ dcn_b) {
    extern __shared__ char B[];
    uint32_t sb = smem_u32(B);
    uint32_t* A32h = (uint32_t*)B;
    uint32_t* A32l = (uint32_t*)(B + OFF_ALO);
    int4*   s_ofs = (int4*)(B + OFF_OFS);
    float4* s_w   = (float4*)(B + OFF_WTS);

    int t = threadIdx.x, lane = t & 31, wid = t >> 5;
    int img = blockIdx.y, n0 = blockIdx.x * 64;
    const float* X = &g_xnhwc[img][0][0];

    float acc[8][4];
#pragma unroll
    for (int nt = 0; nt < 8; nt++)
#pragma unroll
        for (int f = 0; f < 4; f++) acc[nt][f] = 0.f;

    int cq = t & 31, pxg = t >> 5;
    int c = cq * 4;
    int wm = wid & 3, wn = wid >> 2;

    uint32_t arow = (lane & 7) + ((lane >> 3) & 1) * 8;
    uint32_t acolB = ((lane >> 4) & 1) * 16;
    uint32_t aAddr0 = sb + (wm * 16 + arow) * 272 + acolB;
    uint32_t brow = (lane & 7) + ((lane >> 4) & 1) * 8;
    uint32_t bcolB = ((lane >> 3) & 1) * 16;
    uint32_t bOff = (wn * 64 + brow) * 272 + bcolB;

    for (int kk = 0; kk < KK9; kk++) {
        __syncthreads();
        prefetch_B(sb, kk, t);

        if (t < 64) {
            int n = n0 + t;
            float dy = g_off[img][n][kk * 2 + 0];
            float dx = g_off[img][n][kk * 2 + 1];
            float py  = (float)((n >> 7) + kk / 3 - 1) + dy;
            float pxf = (float)((n & 127) + kk % 3 - 1) + dx;
            float y0f = floorf(py), x0f = floorf(pxf);
            int y0 = (int)y0f, x0 = (int)x0f;
            float wy = py - y0f, wx = pxf - x0f;
            int y1 = y0 + 1, x1 = x0 + 1;
            bool vy0 = (unsigned)y0 < (unsigned)Hh, vy1 = (unsigned)y1 < (unsigned)Hh;
            bool vx0 = (unsigned)x0 < (unsigned)Ww, vx1 = (unsigned)x1 < (unsigned)Ww;
            int yc0 = min(max(y0, 0), Hh - 1), yc1 = min(max(y1, 0), Hh - 1);
            int xc0 = min(max(x0, 0), Ww - 1), xc1 = min(max(x1, 0), Ww - 1);
            s_ofs[t] = make_int4((yc0 * Ww + xc0) * Cc, (yc0 * Ww + xc1) * Cc,
                                 (yc1 * Ww + xc0) * Cc, (yc1 * Ww + xc1) * Cc);
            s_w[t] = make_float4(vy0 && vx0 ? (1.f - wy) * (1.f - wx) : 0.f,
                                 vy0 && vx1 ? (1.f - wy) * wx : 0.f,
                                 vy1 && vx0 ? wy * (1.f - wx) : 0.f,
                                 vy1 && vx1 ? wy * wx : 0.f);
        }
        __syncthreads();

#pragma unroll 4
        for (int i = 0; i < 8; i++) {
            int px = pxg + i * 8;
            int4  o = s_ofs[px];
            float4 w = s_w[px];
            float4 v0 = *(const float4*)(X + o.x + c);
            float4 v1 = *(const float4*)(X + o.y + c);
            float4 v2 = *(const float4*)(X + o.z + c);
            float4 v3 = *(const float4*)(X + o.w + c);
            float s0 = w.x * v0.x + w.y * v1.x + w.z * v2.x + w.w * v3.x;
            float s1 = w.x * v0.y + w.y * v1.y + w.z * v2.y + w.w * v3.y;
            float s2 = w.x * v0.z + w.y * v1.z + w.z * v2.z + w.w * v3.z;
            float s3 = w.x * v0.w + w.y * v1.w + w.z * v2.w + w.w * v3.w;
            half2 h01 = __floats2half2_rn(s0, s1);
            half2 h23 = __floats2half2_rn(s2, s3);
            float2 f01 = __half22float2(h01), f23 = __half22float2(h23);
            half2 l01 = __floats2half2_rn(s0 - f01.x, s1 - f01.y);
            half2 l23 = __floats2half2_rn(s2 - f23.x, s3 - f23.y);
            *(uint2*)&A32h[px * PA + cq * 2] =
                make_uint2(*(uint32_t*)&h01, *(uint32_t*)&h23);
            *(uint2*)&A32l[px * PA + cq * 2] =
                make_uint2(*(uint32_t*)&l01, *(uint32_t*)&l23);
        }
        asm volatile("cp.async.wait_group 0;" ::: "memory");
        __syncthreads();

        uint32_t bh_base = sb + OFF_BHI + bOff;
        uint32_t bl_base = sb + OFF_BLO + bOff;

#pragma unroll
        for (int kt = 0; kt < 8; kt++) {
            uint32_t kB = kt * 32;
            uint32_t ah[4], al[4], bh[4][4], bl[4][4];
            ldm4(ah, aAddr0 + kB);
            ldm4(al, aAddr0 + OFF_ALO + kB);
#pragma unroll
            for (int ntq = 0; ntq < 4; ntq++) {
                ldm4(bh[ntq], bh_base + ntq * 16 * 272 + kB);
                ldm4(bl[ntq], bl_base + ntq * 16 * 272 + kB);
            }
#pragma unroll
            for (int ntq = 0; ntq < 4; ntq++) {
#pragma unroll
                for (int sub = 0; sub < 2; sub++) {
                    int nt = ntq * 2 + sub;
                    uint32_t b0h = bh[ntq][sub * 2], b1h = bh[ntq][sub * 2 + 1];
                    uint32_t b0l = bl[ntq][sub * 2], b1l = bl[ntq][sub * 2 + 1];
                    mma16816(acc[nt], ah[0], ah[1], ah[2], ah[3], b0h, b1h);
                    mma16816(acc[nt], al[0], al[1], al[2], al[3], b0h, b1h);
                    mma16816(acc[nt], ah[0], ah[1], ah[2], ah[3], b0l, b1l);
                }
            }
        }
    }

    int r0 = wm * 16 + (lane >> 2);
#pragma unroll
    for (int nt = 0; nt < 8; nt++) {
        int col = wn * 64 + nt * 8 + (lane & 3) * 2;
        float2 bias = *(const float2*)(dcn_b + col);
        float2 o0 = make_float2(acc[nt][0] + bias.x, acc[nt][1] + bias.y);
        float2 o1 = make_float2(acc[nt][2] + bias.x, acc[nt][3] + bias.y);
        *(float2*)&g_xd[img][n0 + r0][col] = o0;
        *(float2*)&g_xd[img][n0 + r0 + 8][col] = o1;
    }
}

// ------------------------------ K4: Gram partials G = Ud^T Vd ----------------
// 128-row chunks (4 x 32-row subtiles), 128 chunks per batch.
__global__ void k4_gpart() {
    __shared__ float Us[32][129];
    __shared__ float Vs[32][129];
    int b = blockIdx.y, chunk = blockIdx.x;
    int n0 = chunk * 128, t = threadIdx.x;
    int il = t & 15, jl = t >> 4;

    float acc[8][8];
#pragma unroll
    for (int ii = 0; ii < 8; ii++)
#pragma unroll
        for (int jj = 0; jj < 8; jj++) acc[ii][jj] = 0.f;
    float colsum = 0.f;

    for (int s = 0; s < 4; s++) {
        __syncthreads();
        for (int idx = t; idx < 32 * 128; idx += 256) {
            int cc = idx & 127, nl = idx >> 7;
            Us[nl][cc] = g_xd[b][n0 + s * 32 + nl][cc];
            Vs[nl][cc] = g_xd[2 + b][n0 + s * 32 + nl][cc];
        }
        __syncthreads();
#pragma unroll 4
        for (int nl = 0; nl < 32; nl++) {
            float av[8], bv[8];
#pragma unroll
            for (int ii = 0; ii < 8; ii++) av[ii] = Us[nl][il + 16 * ii];
#pragma unroll
            for (int jj = 0; jj < 8; jj++) bv[jj] = Vs[nl][jl + 16 * jj];
#pragma unroll
            for (int ii = 0; ii < 8; ii++)
#pragma unroll
                for (int jj = 0; jj < 8; jj++) acc[ii][jj] += av[ii] * bv[jj];
        }
        if (t < 128) {
            for (int nl = 0; nl < 32; nl++) colsum += Us[nl][t];
        } else {
            int cc = t - 128;
            for (int nl = 0; nl < 32; nl++) colsum += Vs[nl][cc];
        }
    }
    if (t < 128) g_sup[b][chunk][t] = colsum;
    else         g_svp[b][chunk][t - 128] = colsum;

    for (int g = 0; g < 4; g++) {
        __syncthreads();
#pragma unroll
        for (int jj = 0; jj < 8; jj++) {
            Us[il][jl + 16 * jj]      = acc[2 * g][jj];
            Us[16 + il][jl + 16 * jj] = acc[2 * g + 1][jj];
        }
        __syncthreads();
        for (int idx = t; idx < 32 * 128; idx += 256) {
            int j = idx & 127, r = idx >> 7;
            g_Gp[b][chunk][(32 * g + r) * 128 + j] = Us[r][j];
        }
    }
}

// ------------------------------ K4b: reduce partials -------------------------
__global__ void k4b_reduce() {
    int idx = blockIdx.x * 256 + threadIdx.x;
    if (idx < Bb * Cc * Cc) {
        int b = idx >> 14;
        int rem = idx & (Cc * Cc - 1);
        float s = 0.f;
        for (int ch = 0; ch < NCHUNK; ch++) s += g_Gp[b][ch][rem];
        g_G[b][rem] = s;
    } else {
        int k = idx - Bb * Cc * Cc;
        if (k < 2 * Bb * Cc) {
            int sel = k >> 8;
            int b = (k >> 7) & 1;
            int c = k & 127;
            float s = 0.f;
            if (sel) { for (int ch = 0; ch < NCHUNK; ch++) s += g_svp[b][ch][c]; g_sv[b][c] = s; }
            else     { for (int ch = 0; ch < NCHUNK; ch++) s += g_sup[b][ch][c]; g_su[b][c] = s; }
        }
    }
}

// ------------------------------ K5: tiny attention math ----------------------
__global__ void k5_attn(const float* __restrict__ q_w, const float* __restrict__ q_b,
                        const float* __restrict__ k_w, const float* __restrict__ k_b,
                        const float* __restrict__ v_w, const float* __restrict__ v_b) {
    __shared__ float P[4][128];
    __shared__ float L[4][128];
    __shared__ float ksv[128];
    __shared__ float qsu[4];
    int b = blockIdx.y;
    int i0 = blockIdx.x * 4;
    int t = threadIdx.x;
    int lane = t & 31, wid = t >> 5;

    if (t < 128) {
        float s = 0.f;
        for (int a = 0; a < 128; a++) s += k_w[t * 128 + a] * g_sv[b][a];
        ksv[t] = s;
    } else if (t < 132) {
        int i = i0 + (t - 128);
        float s = 0.f;
        for (int a = 0; a < 128; a++) s += q_w[i * 128 + a] * g_su[b][a];
        qsu[t - 128] = s;
    }
    __syncthreads();

    for (int idx = t; idx < 4 * 128; idx += 256) {
        int a = idx & 127, ii = idx >> 7;
        int i = i0 + ii;
        float s = 0.f;
        for (int m = 0; m < 128; m++) s += q_w[i * 128 + m] * g_G[b][m * 128 + a];
        P[ii][a] = s;
    }
    __syncthreads();

    const float scale = 0.088388347648318447f; // 128^-0.5
    for (int idx = t; idx < 4 * 128; idx += 256) {
        int j = idx & 127, ii = idx >> 7;
        int i = i0 + ii;
        float s = 0.f;
        for (int a = 0; a < 128; a++) s += P[ii][a] * k_w[j * 128 + a];
        s += qsu[ii] * k_b[j] + q_b[i] * ksv[j] + (float)Nn * q_b[i] * k_b[j];
        L[ii][j] = s * scale;
    }
    __syncthreads();

    if (wid < 4) {
        int r = wid;
        float v[4];
        float m = -1e30f;
#pragma unroll
        for (int q = 0; q < 4; q++) { v[q] = L[r][lane + 32 * q]; m = fmaxf(m, v[q]); }
#pragma unroll
        for (int o = 16; o > 0; o >>= 1) m = fmaxf(m, __shfl_xor_sync(0xFFFFFFFFu, m, o));
        float s = 0.f;
#pragma unroll
        for (int q = 0; q < 4; q++) { v[q] = expf(v[q] - m); s += v[q]; }
#pragma unroll
        for (int o = 16; o > 0; o >>= 1) s += __shfl_xor_sync(0xFFFFFFFFu, s, o);
        float inv = 1.f / s;
#pragma unroll
        for (int q = 0; q < 4; q++) L[r][lane + 32 * q] = v[q] * inv;
    }
    __syncthreads();

    for (int idx = t; idx < 4 * 128; idx += 256) {
        int m = idx & 127, ii = idx >> 7;
        float s = 0.f;
        for (int j = 0; j < 128; j++) s += L[ii][j] * v_w[j * 128 + m];
        g_Mt[b][m * 128 + (i0 + ii)] = s;
    }
    if (t < 4) {
        float s = 0.f;
        for (int j = 0; j < 128; j++) s += L[t][j] * v_b[j];
        g_r[b][i0 + t] = s;
    }
}

// ------------------------------ K6: out = M @ Vd^T + r -----------------------
__global__ void k6_out(float* __restrict__ out) {
    __shared__ float Ms[32][129];
    __shared__ float Vs[32][129];
    int b = blockIdx.y, n0 = blockIdx.x * 128, t = threadIdx.x;
    int il = t & 15, jl = t >> 4;

    float acc[8][8];
#pragma unroll
    for (int ii = 0; ii < 8; ii++)
#pragma unroll
        for (int jj = 0; jj < 8; jj++) acc[ii][jj] = 0.f;

    for (int s = 0; s < 4; s++) {
        __syncthreads();
        for (int idx = t; idx < 32 * 128; idx += 256) {
            int i = idx & 127, mm = idx >> 7;
            Ms[mm][i] = g_Mt[b][(s * 32 + mm) * 128 + i];
        }
        for (int idx = t; idx < 32 * 128; idx += 256) {
            int mmr = idx & 31, nl = idx >> 5;
            Vs[mmr][nl] = g_xd[2 + b][n0 + nl][s * 32 + mmr];
        }
        __syncthreads();
#pragma unroll 4
        for (int mm = 0; mm < 32; mm++) {
            float av[8], bv[8];
#pragma unroll
            for (int ii = 0; ii < 8; ii++) av[ii] = Ms[mm][il + 16 * ii];
#pragma unroll
            for (int jj = 0; jj < 8; jj++) bv[jj] = Vs[mm][jl + 16 * jj];
#pragma unroll
            for (int ii = 0; ii < 8; ii++)
#pragma unroll
                for (int jj = 0; jj < 8; jj++) acc[ii][jj] += av[ii] * bv[jj];
        }
    }

    for (int g = 0; g < 4; g++) {
        __syncthreads();
#pragma unroll
        for (int jj = 0; jj < 8; jj++) {
            Ms[il][jl + 16 * jj]      = acc[2 * g][jj];
            Ms[16 + il][jl + 16 * jj] = acc[2 * g + 1][jj];
        }
        __syncthreads();
        for (int idx = t; idx < 32 * 128; idx += 256) {
            int j = idx & 127, r = idx >> 7;
            int i = 32 * g + r;
            out[(size_t)(b * Cc + i) * Nn + n0 + j] = Ms[r][j] + g_r[b][i];
        }
    }
}

// ------------------------------ launch ---------------------------------------
extern "C" void kernel_launch(void* const* d_in, const int* in_sizes, int n_in,
                              void* d_out, int out_size) {
    (void)in_sizes; (void)n_in; (void)out_size;
    const float* u        = (const float*)d_in[0];
    const float* v        = (const float*)d_in[1];
    const float* offset_w = (const float*)d_in[2];
    const float* offset_b = (const float*)d_in[3];
    const float* dcn_w    = (const float*)d_in[4];
    const float* dcn_b    = (const float*)d_in[5];
    const float* q_w      = (const float*)d_in[6];
    const float* q_b      = (const float*)d_in[7];
    const float* k_w      = (const float*)d_in[8];
    const float* k_b      = (const float*)d_in[9];
    const float* v_w      = (const float*)d_in[10];
    const float* v_b      = (const float*)d_in[11];
    float* out = (float*)d_out;

    cudaFuncSetAttribute(k1_offset, cudaFuncAttributeMaxDynamicSharedMemorySize, K1_DYN);
    cudaFuncSetAttribute(k3_deform, cudaFuncAttributeMaxDynamicSharedMemorySize, K3_DYN);

    k0_prep<<<(KK9 * Cc * Cc + 255) / 256, 256>>>(dcn_w, offset_w);
    k2_transpose<<<dim3(Nn / 32, Cc / 32, NIMG), dim3(32, 8)>>>(u, v);
    k1_offset<<<dim3(Hh, NIMG), 256, K1_DYN>>>(offset_b);
    k3_deform<<<dim3(Nn / 64, NIMG), 256, K3_DYN>>>(dcn_b);
    k4_gpart<<<dim3(NCHUNK, Bb), 256>>>();
    k4b_reduce<<<130, 256>>>();
    k5_attn<<<dim3(32, Bb), 256>>>(q_w, q_b, k_w, k_b, v_w, v_b);
    k6_out<<<dim3(Nn / 128, Bb), 256>>>(out);
}

// round 14
// speedup vs baseline: 1.2514x; 1.1689x over previous
#include <cuda_runtime.h>
#include <cuda_fp16.h>
#include <math.h>
#include <stdint.h>

#define Hh 128
#define Ww 128
#define Cc 128
#define Nn (Hh*Ww)
#define Bb 2
#define NIMG 4          // img = tensor*2 + batch ; tensor 0 = u, 1 = v
#define KK9 9
#define OCH 18
#define NCHUNK 128

// -------- scratch (static device allocations; no runtime alloc allowed) ------
__device__ float g_xnhwc[NIMG][Nn][Cc];   // inputs transposed to NHWC (fp32)
__device__ __half g_xh[NIMG][Nn][Cc];     // x hi-half
__device__ __half g_xl[NIMG][Nn][Cc];     // x lo-half
__device__ float g_off[NIMG][Nn][OCH];    // offset conv output, per-pixel 18 vals
__device__ float g_xd[NIMG][Nn][Cc];      // deformable conv outputs (NHWC)
__device__ __half g_Wh[KK9][Cc][Cc];      // dcn_w hi-half [kk][co][c]
__device__ __half g_Wl[KK9][Cc][Cc];      // dcn_w lo-half (k1-precision only)
__device__ __half g_Woh[KK9][32][Cc];     // offset_w hi [tap][out(pad32)][c]
__device__ __half g_Wol[KK9][32][Cc];     // offset_w lo
__device__ float g_Gp[Bb][NCHUNK][Cc*Cc]; // Gram partials
__device__ float g_sup[Bb][NCHUNK][Cc];
__device__ float g_svp[Bb][NCHUNK][Cc];
__device__ float g_G[Bb][Cc*Cc];
__device__ float g_su[Bb][Cc];
__device__ float g_sv[Bb][Cc];
__device__ float g_Mt[Bb][Cc*Cc];         // (attn @ Vw)^T  [m][i]
__device__ float g_r[Bb][Cc];             // attn @ vb

// ------------------------------ common helpers -------------------------------
__device__ __forceinline__ void mma16816(float* d, uint32_t a0, uint32_t a1,
                                         uint32_t a2, uint32_t a3,
                                         uint32_t b0, uint32_t b1) {
    asm volatile(
        "mma.sync.aligned.m16n8k16.row.col.f32.f16.f16.f32 "
        "{%0,%1,%2,%3}, {%4,%5,%6,%7}, {%8,%9}, {%0,%1,%2,%3};"
        : "+f"(d[0]), "+f"(d[1]), "+f"(d[2]), "+f"(d[3])
        : "r"(a0), "r"(a1), "r"(a2), "r"(a3), "r"(b0), "r"(b1));
}
__device__ __forceinline__ uint32_t smem_u32(const void* p) {
    uint32_t a;
    asm("{ .reg .u64 t; cvta.to.shared.u64 t, %1; cvt.u32.u64 %0, t; }" : "=r"(a) : "l"(p));
    return a;
}
__device__ __forceinline__ void ldm4(uint32_t* r, uint32_t addr) {
    asm volatile("ldmatrix.sync.aligned.m8n8.x4.shared.b16 {%0,%1,%2,%3}, [%4];"
                 : "=r"(r[0]), "=r"(r[1]), "=r"(r[2]), "=r"(r[3]) : "r"(addr));
}
__device__ __forceinline__ void cp16(uint32_t s, const void* g) {
    asm volatile("cp.async.cg.shared.global [%0], [%1], 16;" :: "r"(s), "l"(g));
}

// ------------------------------ K0: weight prep ------------------------------
__global__ void k0_prep(const float* __restrict__ dcn_w,
                        const float* __restrict__ offset_w) {
    int idx = blockIdx.x * blockDim.x + threadIdx.x;
    if (idx < KK9 * Cc * Cc) {
        int kk = idx / (Cc * Cc);
        int rem = idx % (Cc * Cc);
        int co = rem >> 7, c = rem & 127;
        float w = dcn_w[(co * Cc + c) * KK9 + kk];
        __half h = __float2half_rn(w);
        __half l = __float2half_rn(w - __half2float(h));
        g_Wh[kk][co][c] = h;
        g_Wl[kk][co][c] = l;
    }
    if (idx < KK9 * 32 * Cc) {
        int tap = idx / (32 * Cc);
        int rem = idx % (32 * Cc);
        int o = rem >> 7, c = rem & 127;
        float w = (o < OCH) ? offset_w[(o * Cc + c) * KK9 + tap] : 0.f;
        __half h = __float2half_rn(w);
        __half l = __float2half_rn(w - __half2float(h));
        g_Woh[tap][o][c] = h;
        g_Wol[tap][o][c] = l;
    }
}

// ------------------------------ K2: NCHW -> NHWC (+ hi/lo split) -------------
__global__ void k2_transpose(const float* __restrict__ u,
                             const float* __restrict__ v) {
    __shared__ float tile[32][33];
    int img = blockIdx.z;
    int t = img >> 1, b = img & 1;
    const float* x = t ? v : u;
    int n0 = blockIdx.x * 32, c0 = blockIdx.y * 32;
    int tx = threadIdx.x, ty = threadIdx.y;
#pragma unroll
    for (int i = 0; i < 32; i += 8)
        tile[ty + i][tx] = x[(size_t)(b * Cc + c0 + ty + i) * Nn + n0 + tx];
    __syncthreads();
#pragma unroll
    for (int i = 0; i < 32; i += 8) {
        float vv = tile[tx][ty + i];
        int n = n0 + ty + i, c = c0 + tx;
        g_xnhwc[img][n][c] = vv;
        __half h = __float2half_rn(vv);
        g_xh[img][n][c] = h;
        g_xl[img][n][c] = __float2half_rn(vv - __half2float(h));
    }
}

// ------------------------------ K1: offset conv via mma fp16x3 ---------------
#define XP 80                       // bytes per 32-ch half row (64 data + 16 pad)
#define XHALF (3 * 130 * XP)        // 31200
#define OFF_XL  XHALF
#define OFF_WH  (2 * XHALF)         // 62400
#define WHALF (KK9 * 32 * XP)       // 23040
#define OFF_WL  (OFF_WH + WHALF)
#define K1_DYN  (OFF_WH + 2 * WHALF)  // 108480

__global__ void __launch_bounds__(256, 2) k1_offset(const float* __restrict__ offset_b) {
    extern __shared__ char S[];
    uint32_t sb = smem_u32(S);
    int t = threadIdx.x, lane = t & 31, wid = t >> 5;
    int y = blockIdx.x, img = blockIdx.y;

    float acc[4][4];
#pragma unroll
    for (int nt = 0; nt < 4; nt++)
#pragma unroll
        for (int f = 0; f < 4; f++) acc[nt][f] = 0.f;

    uint32_t arow = (lane & 7) + ((lane >> 3) & 1) * 8;
    uint32_t acolB = ((lane >> 4) & 1) * 16;
    uint32_t brow = (lane & 7) + ((lane >> 4) & 1) * 8;
    uint32_t bcolB = ((lane >> 3) & 1) * 16;
    int wm = wid;                    // 8 warps x m16 = 128 px

    for (int ch = 0; ch < 4; ch++) {
        __syncthreads();             // prev chunk mma done
        for (int i = t * 16; i < 2 * XHALF; i += 256 * 16)
            *(float4*)(S + i) = make_float4(0.f, 0.f, 0.f, 0.f);
        __syncthreads();
        // x rows: hi chunks [0,1536), lo [1536,3072)
#pragma unroll
        for (int j = 0; j < 12; j++) {
            int idx = t + 256 * j;
            int sel = (idx >= 1536) ? 1 : 0;
            int i2 = idx - sel * 1536;
            int row3 = i2 >> 9;
            int win = i2 & 511;
            int px = win >> 2, c16 = win & 3;
            int gy = y + row3 - 1;
            if ((unsigned)gy < (unsigned)Hh) {
                const __half* gsrc = sel ? &g_xl[img][gy * Ww + px][ch * 32 + c16 * 8]
                                         : &g_xh[img][gy * Ww + px][ch * 32 + c16 * 8];
                cp16(sb + sel * XHALF + ((row3 * 130) + px + 1) * XP + c16 * 16, gsrc);
            }
        }
#pragma unroll
        for (int j = 0; j < 9; j++) {
            int idx = t + 256 * j;
            int sel = (idx >= 1152) ? 1 : 0;
            int i2 = idx - sel * 1152;
            int tap = i2 >> 7;
            int win = i2 & 127;
            int o = win >> 2, c16 = win & 3;
            const __half* gsrc = sel ? &g_Wol[tap][o][ch * 32 + c16 * 8]
                                     : &g_Woh[tap][o][ch * 32 + c16 * 8];
            cp16(sb + OFF_WH + sel * WHALF + (tap * 32 + o) * XP + c16 * 16, gsrc);
        }
        asm volatile("cp.async.commit_group;" ::: "memory");
        asm volatile("cp.async.wait_group 0;" ::: "memory");
        __syncthreads();

#pragma unroll
        for (int tap = 0; tap < KK9; tap++) {
            int di = tap / 3, dj = tap % 3;
            uint32_t abase = sb + ((uint32_t)(di * 130 + dj + wm * 16) + arow) * XP + acolB;
            uint32_t bbase = sb + OFF_WH + (tap * 32 + brow) * XP + bcolB;
#pragma unroll
            for (int ks = 0; ks < 2; ks++) {
                uint32_t kB = ks * 32;
                uint32_t ah[4], al[4], bh[2][4], bl[2][4];
                ldm4(ah, abase + kB);
                ldm4(al, abase + XHALF + kB);
                ldm4(bh[0], bbase + kB);
                ldm4(bh[1], bbase + 16 * XP + kB);
                ldm4(bl[0], bbase + WHALF + kB);
                ldm4(bl[1], bbase + WHALF + 16 * XP + kB);
#pragma unroll
                for (int ntq = 0; ntq < 2; ntq++) {
#pragma unroll
                    for (int sub = 0; sub < 2; sub++) {
                        int nt = ntq * 2 + sub;
                        uint32_t b0h = bh[ntq][sub * 2], b1h = bh[ntq][sub * 2 + 1];
                        uint32_t b0l = bl[ntq][sub * 2], b1l = bl[ntq][sub * 2 + 1];
                        mma16816(acc[nt], ah[0], ah[1], ah[2], ah[3], b0h, b1h);
                        mma16816(acc[nt], al[0], al[1], al[2], al[3], b0h, b1h);
                        mma16816(acc[nt], ah[0], ah[1], ah[2], ah[3], b0l, b1l);
                    }
                }
            }
        }
    }

    int px0 = wm * 16 + (lane >> 2);
    int nbase = y * Ww;
#pragma unroll
    for (int nt = 0; nt < 4; nt++) {
        int col = nt * 8 + (lane & 3) * 2;
        if (col < OCH) {
            float b0 = offset_b[col], b1 = offset_b[col + 1];
            g_off[img][nbase + px0][col]     = acc[nt][0] + b0;
            g_off[img][nbase + px0][col + 1] = acc[nt][1] + b1;
            g_off[img][nbase + px0 + 8][col]     = acc[nt][2] + b0;
            g_off[img][nbase + px0 + 8][col + 1] = acc[nt][3] + b1;
        }
    }
}

// ------------------------------ K3: deformable conv via mma.sync fp16x2 ------
// Block: 64 px x 128 co, 256 threads (8 warps = 4 m16 x 2 n64), 3 blocks/SM.
// 2-pass split: Ahi*Bhi + Alo*Bhi (B-lo correction dropped; weight-quantization
// error ~7e-5 relative, well under the 1e-3 gate). B hi-only halves smem.
#define PA 68                       // u32 row pitch (272 bytes)
#define MATB (128 * PA * 4)         // 34816 bytes (B hi matrix)
#define MATA (64 * PA * 4)          // 17408 bytes (A half-matrix)
#define OFF_ALO  MATA
#define OFF_BHI  (2 * MATA)
#define OFF_OFS  (2 * MATA + MATB)              // int4[64]
#define OFF_WTS  (2 * MATA + MATB + 1024)       // float4[64]
#define K3_DYN   (2 * MATA + MATB + 2048)       // 71680 -> 3 blocks/SM

__device__ __forceinline__ void prefetch_B(uint32_t sb, int kk, int t) {
    uint32_t base = sb + OFF_BHI;
#pragma unroll
    for (int j = 0; j < 8; j++) {
        int chunk = t + 256 * j;              // 0..2047 (hi only)
        int row = chunk >> 4, ch16 = chunk & 15;
        cp16(base + (row * PA + ch16 * 4) * 4, &g_Wh[kk][row][ch16 * 8]);
    }
    asm volatile("cp.async.commit_group;" ::: "memory");
}

__global__ void __launch_bounds__(256, 3) k3_deform(const float* __restrict__ dcn_b) {
    extern __shared__ char B[];
    uint32_t sb = smem_u32(B);
    uint32_t* A32h = (uint32_t*)B;
    uint32_t* A32l = (uint32_t*)(B + OFF_ALO);
    int4*   s_ofs = (int4*)(B + OFF_OFS);
    float4* s_w   = (float4*)(B + OFF_WTS);

    int t = threadIdx.x, lane = t & 31, wid = t >> 5;
    int img = blockIdx.y, n0 = blockIdx.x * 64;
    const float* X = &g_xnhwc[img][0][0];

    float acc[8][4];
#pragma unroll
    for (int nt = 0; nt < 8; nt++)
#pragma unroll
        for (int f = 0; f < 4; f++) acc[nt][f] = 0.f;

    int cq = t & 31, pxg = t >> 5;
    int c = cq * 4;
    int wm = wid & 3, wn = wid >> 2;

    uint32_t arow = (lane & 7) + ((lane >> 3) & 1) * 8;
    uint32_t acolB = ((lane >> 4) & 1) * 16;
    uint32_t aAddr0 = sb + (wm * 16 + arow) * 272 + acolB;
    uint32_t brow = (lane & 7) + ((lane >> 4) & 1) * 8;
    uint32_t bcolB = ((lane >> 3) & 1) * 16;
    uint32_t bOff = (wn * 64 + brow) * 272 + bcolB;

    for (int kk = 0; kk < KK9; kk++) {
        __syncthreads();
        prefetch_B(sb, kk, t);

        if (t < 64) {
            int n = n0 + t;
            float dy = g_off[img][n][kk * 2 + 0];
            float dx = g_off[img][n][kk * 2 + 1];
            float py  = (float)((n >> 7) + kk / 3 - 1) + dy;
            float pxf = (float)((n & 127) + kk % 3 - 1) + dx;
            float y0f = floorf(py), x0f = floorf(pxf);
            int y0 = (int)y0f, x0 = (int)x0f;
            float wy = py - y0f, wx = pxf - x0f;
            int y1 = y0 + 1, x1 = x0 + 1;
            bool vy0 = (unsigned)y0 < (unsigned)Hh, vy1 = (unsigned)y1 < (unsigned)Hh;
            bool vx0 = (unsigned)x0 < (unsigned)Ww, vx1 = (unsigned)x1 < (unsigned)Ww;
            int yc0 = min(max(y0, 0), Hh - 1), yc1 = min(max(y1, 0), Hh - 1);
            int xc0 = min(max(x0, 0), Ww - 1), xc1 = min(max(x1, 0), Ww - 1);
            s_ofs[t] = make_int4((yc0 * Ww + xc0) * Cc, (yc0 * Ww + xc1) * Cc,
                                 (yc1 * Ww + xc0) * Cc, (yc1 * Ww + xc1) * Cc);
            s_w[t] = make_float4(vy0 && vx0 ? (1.f - wy) * (1.f - wx) : 0.f,
                                 vy0 && vx1 ? (1.f - wy) * wx : 0.f,
                                 vy1 && vx0 ? wy * (1.f - wx) : 0.f,
                                 vy1 && vx1 ? wy * wx : 0.f);
        }
        __syncthreads();

#pragma unroll 4
        for (int i = 0; i < 8; i++) {
            int px = pxg + i * 8;
            int4  o = s_ofs[px];
            float4 w = s_w[px];
            float4 v0 = *(const float4*)(X + o.x + c);
            float4 v1 = *(const float4*)(X + o.y + c);
            float4 v2 = *(const float4*)(X + o.z + c);
            float4 v3 = *(const float4*)(X + o.w + c);
            float s0 = w.x * v0.x + w.y * v1.x + w.z * v2.x + w.w * v3.x;
            float s1 = w.x * v0.y + w.y * v1.y + w.z * v2.y + w.w * v3.y;
            float s2 = w.x * v0.z + w.y * v1.z + w.z * v2.z + w.w * v3.z;
            float s3 = w.x * v0.w + w.y * v1.w + w.z * v2.w + w.w * v3.w;
            half2 h01 = __floats2half2_rn(s0, s1);
            half2 h23 = __floats2half2_rn(s2, s3);
            float2 f01 = __half22float2(h01), f23 = __half22float2(h23);
            half2 l01 = __floats2half2_rn(s0 - f01.x, s1 - f01.y);
            half2 l23 = __floats2half2_rn(s2 - f23.x, s3 - f23.y);
            *(uint2*)&A32h[px * PA + cq * 2] =
                make_uint2(*(uint32_t*)&h01, *(uint32_t*)&h23);
            *(uint2*)&A32l[px * PA + cq * 2] =
                make_uint2(*(uint32_t*)&l01, *(uint32_t*)&l23);
        }
        asm volatile("cp.async.wait_group 0;" ::: "memory");
        __syncthreads();

        uint32_t bh_base = sb + OFF_BHI + bOff;

        // ---- mma: 8 k16-steps x 2 passes (hi*Bhi + lo*Bhi) ----
#pragma unroll
        for (int kt = 0; kt < 8; kt++) {
            uint32_t kB = kt * 32;
            uint32_t ah[4], al[4], bh[4][4];
            ldm4(ah, aAddr0 + kB);
            ldm4(al, aAddr0 + OFF_ALO + kB);
#pragma unroll
            for (int ntq = 0; ntq < 4; ntq++)
                ldm4(bh[ntq], bh_base + ntq * 16 * 272 + kB);
#pragma unroll
            for (int ntq = 0; ntq < 4; ntq++) {
#pragma unroll
                for (int sub = 0; sub < 2; sub++) {
                    int nt = ntq * 2 + sub;
                    uint32_t b0h = bh[ntq][sub * 2], b1h = bh[ntq][sub * 2 + 1];
                    mma16816(acc[nt], ah[0], ah[1], ah[2], ah[3], b0h, b1h);
                    mma16816(acc[nt], al[0], al[1], al[2], al[3], b0h, b1h);
                }
            }
        }
    }

    int r0 = wm * 16 + (lane >> 2);
#pragma unroll
    for (int nt = 0; nt < 8; nt++) {
        int col = wn * 64 + nt * 8 + (lane & 3) * 2;
        float2 bias = *(const float2*)(dcn_b + col);
        float2 o0 = make_float2(acc[nt][0] + bias.x, acc[nt][1] + bias.y);
        float2 o1 = make_float2(acc[nt][2] + bias.x, acc[nt][3] + bias.y);
        *(float2*)&g_xd[img][n0 + r0][col] = o0;
        *(float2*)&g_xd[img][n0 + r0 + 8][col] = o1;
    }
}

// ------------------------------ K4: Gram partials G = Ud^T Vd ----------------
// 128-row chunks (4 x 32-row subtiles), 128 chunks per batch.
__global__ void k4_gpart() {
    __shared__ float Us[32][129];
    __shared__ float Vs[32][129];
    int b = blockIdx.y, chunk = blockIdx.x;
    int n0 = chunk * 128, t = threadIdx.x;
    int il = t & 15, jl = t >> 4;

    float acc[8][8];
#pragma unroll
    for (int ii = 0; ii < 8; ii++)
#pragma unroll
        for (int jj = 0; jj < 8; jj++) acc[ii][jj] = 0.f;
    float colsum = 0.f;

    for (int s = 0; s < 4; s++) {
        __syncthreads();
        for (int idx = t; idx < 32 * 128; idx += 256) {
            int cc = idx & 127, nl = idx >> 7;
            Us[nl][cc] = g_xd[b][n0 + s * 32 + nl][cc];
            Vs[nl][cc] = g_xd[2 + b][n0 + s * 32 + nl][cc];
        }
        __syncthreads();
#pragma unroll 4
        for (int nl = 0; nl < 32; nl++) {
            float av[8], bv[8];
#pragma unroll
            for (int ii = 0; ii < 8; ii++) av[ii] = Us[nl][il + 16 * ii];
#pragma unroll
            for (int jj = 0; jj < 8; jj++) bv[jj] = Vs[nl][jl + 16 * jj];
#pragma unroll
            for (int ii = 0; ii < 8; ii++)
#pragma unroll
                for (int jj = 0; jj < 8; jj++) acc[ii][jj] += av[ii] * bv[jj];
        }
        if (t < 128) {
            for (int nl = 0; nl < 32; nl++) colsum += Us[nl][t];
        } else {
            int cc = t - 128;
            for (int nl = 0; nl < 32; nl++) colsum += Vs[nl][cc];
        }
    }
    if (t < 128) g_sup[b][chunk][t] = colsum;
    else         g_svp[b][chunk][t - 128] = colsum;

    for (int g = 0; g < 4; g++) {
        __syncthreads();
#pragma unroll
        for (int jj = 0; jj < 8; jj++) {
            Us[il][jl + 16 * jj]      = acc[2 * g][jj];
            Us[16 + il][jl + 16 * jj] = acc[2 * g + 1][jj];
        }
        __syncthreads();
        for (int idx = t; idx < 32 * 128; idx += 256) {
            int j = idx & 127, r = idx >> 7;
            g_Gp[b][chunk][(32 * g + r) * 128 + j] = Us[r][j];
        }
    }
}

// ------------------------------ K4b: reduce partials -------------------------
__global__ void k4b_reduce() {
    int idx = blockIdx.x * 256 + threadIdx.x;
    if (idx < Bb * Cc * Cc) {
        int b = idx >> 14;
        int rem = idx & (Cc * Cc - 1);
        float s = 0.f;
        for (int ch = 0; ch < NCHUNK; ch++) s += g_Gp[b][ch][rem];
        g_G[b][rem] = s;
    } else {
        int k = idx - Bb * Cc * Cc;
        if (k < 2 * Bb * Cc) {
            int sel = k >> 8;
            int b = (k >> 7) & 1;
            int c = k & 127;
            float s = 0.f;
            if (sel) { for (int ch = 0; ch < NCHUNK; ch++) s += g_svp[b][ch][c]; g_sv[b][c] = s; }
            else     { for (int ch = 0; ch < NCHUNK; ch++) s += g_sup[b][ch][c]; g_su[b][c] = s; }
        }
    }
}

// ------------------------------ K5: tiny attention math ----------------------
__global__ void k5_attn(const float* __restrict__ q_w, const float* __restrict__ q_b,
                        const float* __restrict__ k_w, const float* __restrict__ k_b,
                        const float* __restrict__ v_w, const float* __restrict__ v_b) {
    __shared__ float P[4][128];
    __shared__ float L[4][128];
    __shared__ float ksv[128];
    __shared__ float qsu[4];
    int b = blockIdx.y;
    int i0 = blockIdx.x * 4;
    int t = threadIdx.x;
    int lane = t & 31, wid = t >> 5;

    if (t < 128) {
        float s = 0.f;
        for (int a = 0; a < 128; a++) s += k_w[t * 128 + a] * g_sv[b][a];
        ksv[t] = s;
    } else if (t < 132) {
        int i = i0 + (t - 128);
        float s = 0.f;
        for (int a = 0; a < 128; a++) s += q_w[i * 128 + a] * g_su[b][a];
        qsu[t - 128] = s;
    }
    __syncthreads();

    for (int idx = t; idx < 4 * 128; idx += 256) {
        int a = idx & 127, ii = idx >> 7;
        int i = i0 + ii;
        float s = 0.f;
        for (int m = 0; m < 128; m++) s += q_w[i * 128 + m] * g_G[b][m * 128 + a];
        P[ii][a] = s;
    }
    __syncthreads();

    const float scale = 0.088388347648318447f; // 128^-0.5
    for (int idx = t; idx < 4 * 128; idx += 256) {
        int j = idx & 127, ii = idx >> 7;
        int i = i0 + ii;
        float s = 0.f;
        for (int a = 0; a < 128; a++) s += P[ii][a] * k_w[j * 128 + a];
        s += qsu[ii] * k_b[j] + q_b[i] * ksv[j] + (float)Nn * q_b[i] * k_b[j];
        L[ii][j] = s * scale;
    }
    __syncthreads();

    if (wid < 4) {
        int r = wid;
        float v[4];
        float m = -1e30f;
#pragma unroll
        for (int q = 0; q < 4; q++) { v[q] = L[r][lane + 32 * q]; m = fmaxf(m, v[q]); }
#pragma unroll
        for (int o = 16; o > 0; o >>= 1) m = fmaxf(m, __shfl_xor_sync(0xFFFFFFFFu, m, o));
        float s = 0.f;
#pragma unroll
        for (int q = 0; q < 4; q++) { v[q] = expf(v[q] - m); s += v[q]; }
#pragma unroll
        for (int o = 16; o > 0; o >>= 1) s += __shfl_xor_sync(0xFFFFFFFFu, s, o);
        float inv = 1.f / s;
#pragma unroll
        for (int q = 0; q < 4; q++) L[r][lane + 32 * q] = v[q] * inv;
    }
    __syncthreads();

    for (int idx = t; idx < 4 * 128; idx += 256) {
        int m = idx & 127, ii = idx >> 7;
        float s = 0.f;
        for (int j = 0; j < 128; j++) s += L[ii][j] * v_w[j * 128 + m];
        g_Mt[b][m * 128 + (i0 + ii)] = s;
    }
    if (t < 4) {
        float s = 0.f;
        for (int j = 0; j < 128; j++) s += L[t][j] * v_b[j];
        g_r[b][i0 + t] = s;
    }
}

// ------------------------------ K6: out = M @ Vd^T + r -----------------------
__global__ void k6_out(float* __restrict__ out) {
    __shared__ float Ms[32][129];
    __shared__ float Vs[32][129];
    int b = blockIdx.y, n0 = blockIdx.x * 128, t = threadIdx.x;
    int il = t & 15, jl = t >> 4;

    float acc[8][8];
#pragma unroll
    for (int ii = 0; ii < 8; ii++)
#pragma unroll
        for (int jj = 0; jj < 8; jj++) acc[ii][jj] = 0.f;

    for (int s = 0; s < 4; s++) {
        __syncthreads();
        for (int idx = t; idx < 32 * 128; idx += 256) {
            int i = idx & 127, mm = idx >> 7;
            Ms[mm][i] = g_Mt[b][(s * 32 + mm) * 128 + i];
        }
        for (int idx = t; idx < 32 * 128; idx += 256) {
            int mmr = idx & 31, nl = idx >> 5;
            Vs[mmr][nl] = g_xd[2 + b][n0 + nl][s * 32 + mmr];
        }
        __syncthreads();
#pragma unroll 4
        for (int mm = 0; mm < 32; mm++) {
            float av[8], bv[8];
#pragma unroll
            for (int ii = 0; ii < 8; ii++) av[ii] = Ms[mm][il + 16 * ii];
#pragma unroll
            for (int jj = 0; jj < 8; jj++) bv[jj] = Vs[mm][jl + 16 * jj];
#pragma unroll
            for (int ii = 0; ii < 8; ii++)
#pragma unroll
                for (int jj = 0; jj < 8; jj++) acc[ii][jj] += av[ii] * bv[jj];
        }
    }

    for (int g = 0; g < 4; g++) {
        __syncthreads();
#pragma unroll
        for (int jj = 0; jj < 8; jj++) {
            Ms[il][jl + 16 * jj]      = acc[2 * g][jj];
            Ms[16 + il][jl + 16 * jj] = acc[2 * g + 1][jj];
        }
        __syncthreads();
        for (int idx = t; idx < 32 * 128; idx += 256) {
            int j = idx & 127, r = idx >> 7;
            int i = 32 * g + r;
            out[(size_t)(b * Cc + i) * Nn + n0 + j] = Ms[r][j] + g_r[b][i];
        }
    }
}

// ------------------------------ launch ---------------------------------------
extern "C" void kernel_launch(void* const* d_in, const int* in_sizes, int n_in,
                              void* d_out, int out_size) {
    (void)in_sizes; (void)n_in; (void)out_size;
    const float* u        = (const float*)d_in[0];
    const float* v        = (const float*)d_in[1];
    const float* offset_w = (const float*)d_in[2];
    const float* offset_b = (const float*)d_in[3];
    const float* dcn_w    = (const float*)d_in[4];
    const float* dcn_b    = (const float*)d_in[5];
    const float* q_w      = (const float*)d_in[6];
    const float* q_b      = (const float*)d_in[7];
    const float* k_w      = (const float*)d_in[8];
    const float* k_b      = (const float*)d_in[9];
    const float* v_w      = (const float*)d_in[10];
    const float* v_b      = (const float*)d_in[11];
    float* out = (float*)d_out;

    cudaFuncSetAttribute(k1_offset, cudaFuncAttributeMaxDynamicSharedMemorySize, K1_DYN);
    cudaFuncSetAttribute(k3_deform, cudaFuncAttributeMaxDynamicSharedMemorySize, K3_DYN);

    k0_prep<<<(KK9 * Cc * Cc + 255) / 256, 256>>>(dcn_w, offset_w);
    k2_transpose<<<dim3(Nn / 32, Cc / 32, NIMG), dim3(32, 8)>>>(u, v);
    k1_offset<<<dim3(Hh, NIMG), 256, K1_DYN>>>(offset_b);
    k3_deform<<<dim3(Nn / 64, NIMG), 256, K3_DYN>>>(dcn_b);
    k4_gpart<<<dim3(NCHUNK, Bb), 256>>>();
    k4b_reduce<<<130, 256>>>();
    k5_attn<<<dim3(32, Bb), 256>>>(q_w, q_b, k_w, k_b, v_w, v_b);
    k6_out<<<dim3(Nn / 128, Bb), 256>>>(out);
}

// round 15
// speedup vs baseline: 1.2663x; 1.0119x over previous
#include <cuda_runtime.h>
#include <cuda_fp16.h>
#include <math.h>
#include <stdint.h>

#define Hh 128
#define Ww 128
#define Cc 128
#define Nn (Hh*Ww)
#define Bb 2
#define NIMG 4          // img = tensor*2 + batch ; tensor 0 = u, 1 = v
#define KK9 9
#define OCH 18
#define NCHUNK 128

// -------- scratch (static device allocations; no runtime alloc allowed) ------
__device__ float g_xnhwc[NIMG][Nn][Cc];   // inputs transposed to NHWC (fp32)
__device__ __half g_xh[NIMG][Nn][Cc];     // x hi-half
__device__ __half g_xl[NIMG][Nn][Cc];     // x lo-half
__device__ float g_off[NIMG][Nn][OCH];    // offset conv output, per-pixel 18 vals
__device__ float g_xd[NIMG][Nn][Cc];      // deformable conv outputs (NHWC)
__device__ __half g_Wh[KK9][Cc][Cc];      // dcn_w hi-half [kk][co][c]
__device__ __half g_Wl[KK9][Cc][Cc];      // dcn_w lo-half (k1-precision only)
__device__ __half g_Woh[KK9][32][Cc];     // offset_w hi [tap][out(pad32)][c]
__device__ __half g_Wol[KK9][32][Cc];     // offset_w lo
__device__ float g_Gp[Bb][NCHUNK][Cc*Cc]; // Gram partials
__device__ float g_sup[Bb][NCHUNK][Cc];
__device__ float g_svp[Bb][NCHUNK][Cc];
__device__ float g_G[Bb][Cc*Cc];
__device__ float g_su[Bb][Cc];
__device__ float g_sv[Bb][Cc];
__device__ float g_Mt[Bb][Cc*Cc];         // (attn @ Vw)^T  [m][i]
__device__ float g_r[Bb][Cc];             // attn @ vb

// ------------------------------ common helpers -------------------------------
__device__ __forceinline__ void mma16816(float* d, uint32_t a0, uint32_t a1,
                                         uint32_t a2, uint32_t a3,
                                         uint32_t b0, uint32_t b1) {
    asm volatile(
        "mma.sync.aligned.m16n8k16.row.col.f32.f16.f16.f32 "
        "{%0,%1,%2,%3}, {%4,%5,%6,%7}, {%8,%9}, {%0,%1,%2,%3};"
        : "+f"(d[0]), "+f"(d[1]), "+f"(d[2]), "+f"(d[3])
        : "r"(a0), "r"(a1), "r"(a2), "r"(a3), "r"(b0), "r"(b1));
}
__device__ __forceinline__ uint32_t smem_u32(const void* p) {
    uint32_t a;
    asm("{ .reg .u64 t; cvta.to.shared.u64 t, %1; cvt.u32.u64 %0, t; }" : "=r"(a) : "l"(p));
    return a;
}
__device__ __forceinline__ void ldm4(uint32_t* r, uint32_t addr) {
    asm volatile("ldmatrix.sync.aligned.m8n8.x4.shared.b16 {%0,%1,%2,%3}, [%4];"
                 : "=r"(r[0]), "=r"(r[1]), "=r"(r[2]), "=r"(r[3]) : "r"(addr));
}
__device__ __forceinline__ void cp16(uint32_t s, const void* g) {
    asm volatile("cp.async.cg.shared.global [%0], [%1], 16;" :: "r"(s), "l"(g));
}

// ------------------------------ K0: weight prep ------------------------------
__global__ void k0_prep(const float* __restrict__ dcn_w,
                        const float* __restrict__ offset_w) {
    int idx = blockIdx.x * blockDim.x + threadIdx.x;
    if (idx < KK9 * Cc * Cc) {
        int kk = idx / (Cc * Cc);
        int rem = idx % (Cc * Cc);
        int co = rem >> 7, c = rem & 127;
        float w = dcn_w[(co * Cc + c) * KK9 + kk];
        __half h = __float2half_rn(w);
        __half l = __float2half_rn(w - __half2float(h));
        g_Wh[kk][co][c] = h;
        g_Wl[kk][co][c] = l;
    }
    if (idx < KK9 * 32 * Cc) {
        int tap = idx / (32 * Cc);
        int rem = idx % (32 * Cc);
        int o = rem >> 7, c = rem & 127;
        float w = (o < OCH) ? offset_w[(o * Cc + c) * KK9 + tap] : 0.f;
        __half h = __float2half_rn(w);
        __half l = __float2half_rn(w - __half2float(h));
        g_Woh[tap][o][c] = h;
        g_Wol[tap][o][c] = l;
    }
}

// ------------------------------ K2: NCHW -> NHWC (+ hi/lo split) -------------
__global__ void k2_transpose(const float* __restrict__ u,
                             const float* __restrict__ v) {
    __shared__ float tile[32][33];
    int img = blockIdx.z;
    int t = img >> 1, b = img & 1;
    const float* x = t ? v : u;
    int n0 = blockIdx.x * 32, c0 = blockIdx.y * 32;
    int tx = threadIdx.x, ty = threadIdx.y;
#pragma unroll
    for (int i = 0; i < 32; i += 8)
        tile[ty + i][tx] = x[(size_t)(b * Cc + c0 + ty + i) * Nn + n0 + tx];
    __syncthreads();
#pragma unroll
    for (int i = 0; i < 32; i += 8) {
        float vv = tile[tx][ty + i];
        int n = n0 + ty + i, c = c0 + tx;
        g_xnhwc[img][n][c] = vv;
        __half h = __float2half_rn(vv);
        g_xh[img][n][c] = h;
        g_xl[img][n][c] = __float2half_rn(vv - __half2float(h));
    }
}

// ------------------------------ K1: offset conv via mma fp16x3 ---------------
// Interior slots are fully overwritten by cp.async each chunk; zeroing happens
// ONCE for halo slots (0,129) and OOB rows only.
#define XP 80                       // bytes per 32-ch half row (64 data + 16 pad)
#define XHALF (3 * 130 * XP)        // 31200
#define OFF_XL  XHALF
#define OFF_WH  (2 * XHALF)         // 62400
#define WHALF (KK9 * 32 * XP)       // 23040
#define OFF_WL  (OFF_WH + WHALF)
#define K1_DYN  (OFF_WH + 2 * WHALF)  // 108480

__global__ void __launch_bounds__(256, 2) k1_offset(const float* __restrict__ offset_b) {
    extern __shared__ char S[];
    uint32_t sb = smem_u32(S);
    int t = threadIdx.x, lane = t & 31, wid = t >> 5;
    int y = blockIdx.x, img = blockIdx.y;

    float acc[4][4];
#pragma unroll
    for (int nt = 0; nt < 4; nt++)
#pragma unroll
        for (int f = 0; f < 4; f++) acc[nt][f] = 0.f;

    // ---- one-time zeroing: halo slots + OOB rows (both halves) ----
    if (t < 12) {
        int half = (t >= 6) ? 1 : 0;
        int k = t - half * 6;
        int r3 = k >> 1;
        int sl = (k & 1) ? 129 : 0;
        char* p = S + half * XHALF + (r3 * 130 + sl) * XP;
#pragma unroll
        for (int b2 = 0; b2 < XP; b2 += 16)
            *(float4*)(p + b2) = make_float4(0.f, 0.f, 0.f, 0.f);
    }
#pragma unroll
    for (int r3 = 0; r3 < 3; r3++) {
        int gy = y + r3 - 1;
        if ((unsigned)gy >= (unsigned)Hh) {
            for (int i = t * 16; i < 130 * XP; i += 256 * 16) {
                *(float4*)(S + r3 * 130 * XP + i) = make_float4(0.f, 0.f, 0.f, 0.f);
                *(float4*)(S + XHALF + r3 * 130 * XP + i) = make_float4(0.f, 0.f, 0.f, 0.f);
            }
        }
    }

    uint32_t arow = (lane & 7) + ((lane >> 3) & 1) * 8;
    uint32_t acolB = ((lane >> 4) & 1) * 16;
    uint32_t brow = (lane & 7) + ((lane >> 4) & 1) * 8;
    uint32_t bcolB = ((lane >> 3) & 1) * 16;
    int wm = wid;                    // 8 warps x m16 = 128 px

    for (int ch = 0; ch < 4; ch++) {
        __syncthreads();             // prev chunk mma done (and initial zero visible)
        // x rows: 3 rows x 128 px x 4 chunks x 2 halves = 3072 cp chunks
#pragma unroll
        for (int j = 0; j < 12; j++) {
            int idx = t + 256 * j;
            int sel = (idx >= 1536) ? 1 : 0;
            int i2 = idx - sel * 1536;
            int row3 = i2 >> 9;
            int win = i2 & 511;
            int px = win >> 2, c16 = win & 3;
            int gy = y + row3 - 1;
            if ((unsigned)gy < (unsigned)Hh) {
                const __half* gsrc = sel ? &g_xl[img][gy * Ww + px][ch * 32 + c16 * 8]
                                         : &g_xh[img][gy * Ww + px][ch * 32 + c16 * 8];
                cp16(sb + sel * XHALF + ((row3 * 130) + px + 1) * XP + c16 * 16, gsrc);
            }
        }
#pragma unroll
        for (int j = 0; j < 9; j++) {
            int idx = t + 256 * j;
            int sel = (idx >= 1152) ? 1 : 0;
            int i2 = idx - sel * 1152;
            int tap = i2 >> 7;
            int win = i2 & 127;
            int o = win >> 2, c16 = win & 3;
            const __half* gsrc = sel ? &g_Wol[tap][o][ch * 32 + c16 * 8]
                                     : &g_Woh[tap][o][ch * 32 + c16 * 8];
            cp16(sb + OFF_WH + sel * WHALF + (tap * 32 + o) * XP + c16 * 16, gsrc);
        }
        asm volatile("cp.async.commit_group;" ::: "memory");
        asm volatile("cp.async.wait_group 0;" ::: "memory");
        __syncthreads();

#pragma unroll
        for (int tap = 0; tap < KK9; tap++) {
            int di = tap / 3, dj = tap % 3;
            uint32_t abase = sb + ((uint32_t)(di * 130 + dj + wm * 16) + arow) * XP + acolB;
            uint32_t bbase = sb + OFF_WH + (tap * 32 + brow) * XP + bcolB;
#pragma unroll
            for (int ks = 0; ks < 2; ks++) {
                uint32_t kB = ks * 32;
                uint32_t ah[4], al[4], bh[2][4], bl[2][4];
                ldm4(ah, abase + kB);
                ldm4(al, abase + XHALF + kB);
                ldm4(bh[0], bbase + kB);
                ldm4(bh[1], bbase + 16 * XP + kB);
                ldm4(bl[0], bbase + WHALF + kB);
                ldm4(bl[1], bbase + WHALF + 16 * XP + kB);
#pragma unroll
                for (int ntq = 0; ntq < 2; ntq++) {
#pragma unroll
                    for (int sub = 0; sub < 2; sub++) {
                        int nt = ntq * 2 + sub;
                        uint32_t b0h = bh[ntq][sub * 2], b1h = bh[ntq][sub * 2 + 1];
                        uint32_t b0l = bl[ntq][sub * 2], b1l = bl[ntq][sub * 2 + 1];
                        mma16816(acc[nt], ah[0], ah[1], ah[2], ah[3], b0h, b1h);
                        mma16816(acc[nt], al[0], al[1], al[2], al[3], b0h, b1h);
                        mma16816(acc[nt], ah[0], ah[1], ah[2], ah[3], b0l, b1l);
                    }
                }
            }
        }
    }

    int px0 = wm * 16 + (lane >> 2);
    int nbase = y * Ww;
#pragma unroll
    for (int nt = 0; nt < 4; nt++) {
        int col = nt * 8 + (lane & 3) * 2;
        if (col < OCH) {
            float b0 = offset_b[col], b1 = offset_b[col + 1];
            g_off[img][nbase + px0][col]     = acc[nt][0] + b0;
            g_off[img][nbase + px0][col + 1] = acc[nt][1] + b1;
            g_off[img][nbase + px0 + 8][col]     = acc[nt][2] + b0;
            g_off[img][nbase + px0 + 8][col + 1] = acc[nt][3] + b1;
        }
    }
}

// ------------------------------ K3: deformable conv via mma.sync fp16x2 ------
// Block: 64 px x 128 co, 256 threads (8 warps = 4 m16 x 2 n64), 3 blocks/SM.
// 2-pass split: Ahi*Bhi + Alo*Bhi (B-lo correction dropped; deterministic
// rel_err 7.5e-4 < 1e-3 gate). B hi-only halves smem vs 3-pass.
#define PA 68                       // u32 row pitch (272 bytes)
#define MATB (128 * PA * 4)         // 34816 bytes (B hi matrix)
#define MATA (64 * PA * 4)          // 17408 bytes (A half-matrix)
#define OFF_ALO  MATA
#define OFF_BHI  (2 * MATA)
#define OFF_OFS  (2 * MATA + MATB)              // int4[64]
#define OFF_WTS  (2 * MATA + MATB + 1024)       // float4[64]
#define K3_DYN   (2 * MATA + MATB + 2048)       // 71680 -> 3 blocks/SM

__device__ __forceinline__ void prefetch_B(uint32_t sb, int kk, int t) {
    uint32_t base = sb + OFF_BHI;
#pragma unroll
    for (int j = 0; j < 8; j++) {
        int chunk = t + 256 * j;              // 0..2047 (hi only)
        int row = chunk >> 4, ch16 = chunk & 15;
        cp16(base + (row * PA + ch16 * 4) * 4, &g_Wh[kk][row][ch16 * 8]);
    }
    asm volatile("cp.async.commit_group;" ::: "memory");
}

__global__ void __launch_bounds__(256, 3) k3_deform(const float* __restrict__ dcn_b) {
    extern __shared__ char B[];
    uint32_t sb = smem_u32(B);
    uint32_t* A32h = (uint32_t*)B;
    uint32_t* A32l = (uint32_t*)(B + OFF_ALO);
    int4*   s_ofs = (int4*)(B + OFF_OFS);
    float4* s_w   = (float4*)(B + OFF_WTS);

    int t = threadIdx.x, lane = t & 31, wid = t >> 5;
    int img = blockIdx.y, n0 = blockIdx.x * 64;
    const float* X = &g_xnhwc[img][0][0];

    float acc[8][4];
#pragma unroll
    for (int nt = 0; nt < 8; nt++)
#pragma unroll
        for (int f = 0; f < 4; f++) acc[nt][f] = 0.f;

    int cq = t & 31, pxg = t >> 5;
    int c = cq * 4;
    int wm = wid & 3, wn = wid >> 2;

    uint32_t arow = (lane & 7) + ((lane >> 3) & 1) * 8;
    uint32_t acolB = ((lane >> 4) & 1) * 16;
    uint32_t aAddr0 = sb + (wm * 16 + arow) * 272 + acolB;
    uint32_t brow = (lane & 7) + ((lane >> 4) & 1) * 8;
    uint32_t bcolB = ((lane >> 3) & 1) * 16;
    uint32_t bOff = (wn * 64 + brow) * 272 + bcolB;

    for (int kk = 0; kk < KK9; kk++) {
        __syncthreads();
        prefetch_B(sb, kk, t);

        if (t < 64) {
            int n = n0 + t;
            float dy = g_off[img][n][kk * 2 + 0];
            float dx = g_off[img][n][kk * 2 + 1];
            float py  = (float)((n >> 7) + kk / 3 - 1) + dy;
            float pxf = (float)((n & 127) + kk % 3 - 1) + dx;
            float y0f = floorf(py), x0f = floorf(pxf);
            int y0 = (int)y0f, x0 = (int)x0f;
            float wy = py - y0f, wx = pxf - x0f;
            int y1 = y0 + 1, x1 = x0 + 1;
            bool vy0 = (unsigned)y0 < (unsigned)Hh, vy1 = (unsigned)y1 < (unsigned)Hh;
            bool vx0 = (unsigned)x0 < (unsigned)Ww, vx1 = (unsigned)x1 < (unsigned)Ww;
            int yc0 = min(max(y0, 0), Hh - 1), yc1 = min(max(y1, 0), Hh - 1);
            int xc0 = min(max(x0, 0), Ww - 1), xc1 = min(max(x1, 0), Ww - 1);
            s_ofs[t] = make_int4((yc0 * Ww + xc0) * Cc, (yc0 * Ww + xc1) * Cc,
                                 (yc1 * Ww + xc0) * Cc, (yc1 * Ww + xc1) * Cc);
            s_w[t] = make_float4(vy0 && vx0 ? (1.f - wy) * (1.f - wx) : 0.f,
                                 vy0 && vx1 ? (1.f - wy) * wx : 0.f,
                                 vy1 && vx0 ? wy * (1.f - wx) : 0.f,
                                 vy1 && vx1 ? wy * wx : 0.f);
        }
        __syncthreads();

#pragma unroll 4
        for (int i = 0; i < 8; i++) {
            int px = pxg + i * 8;
            int4  o = s_ofs[px];
            float4 w = s_w[px];
            float4 v0 = *(const float4*)(X + o.x + c);
            float4 v1 = *(const float4*)(X + o.y + c);
            float4 v2 = *(const float4*)(X + o.z + c);
            float4 v3 = *(const float4*)(X + o.w + c);
            float s0 = w.x * v0.x + w.y * v1.x + w.z * v2.x + w.w * v3.x;
            float s1 = w.x * v0.y + w.y * v1.y + w.z * v2.y + w.w * v3.y;
            float s2 = w.x * v0.z + w.y * v1.z + w.z * v2.z + w.w * v3.z;
            float s3 = w.x * v0.w + w.y * v1.w + w.z * v2.w + w.w * v3.w;
            half2 h01 = __floats2half2_rn(s0, s1);
            half2 h23 = __floats2half2_rn(s2, s3);
            float2 f01 = __half22float2(h01), f23 = __half22float2(h23);
            half2 l01 = __floats2half2_rn(s0 - f01.x, s1 - f01.y);
            half2 l23 = __floats2half2_rn(s2 - f23.x, s3 - f23.y);
            *(uint2*)&A32h[px * PA + cq * 2] =
                make_uint2(*(uint32_t*)&h01, *(uint32_t*)&h23);
            *(uint2*)&A32l[px * PA + cq * 2] =
                make_uint2(*(uint32_t*)&l01, *(uint32_t*)&l23);
        }
        asm volatile("cp.async.wait_group 0;" ::: "memory");
        __syncthreads();

        uint32_t bh_base = sb + OFF_BHI + bOff;

        // ---- mma: 8 k16-steps x 2 passes (hi*Bhi + lo*Bhi) ----
#pragma unroll
        for (int kt = 0; kt < 8; kt++) {
            uint32_t kB = kt * 32;
            uint32_t ah[4], al[4], bh[4][4];
            ldm4(ah, aAddr0 + kB);
            ldm4(al, aAddr0 + OFF_ALO + kB);
#pragma unroll
            for (int ntq = 0; ntq < 4; ntq++)
                ldm4(bh[ntq], bh_base + ntq * 16 * 272 + kB);
#pragma unroll
            for (int ntq = 0; ntq < 4; ntq++) {
#pragma unroll
                for (int sub = 0; sub < 2; sub++) {
                    int nt = ntq * 2 + sub;
                    uint32_t b0h = bh[ntq][sub * 2], b1h = bh[ntq][sub * 2 + 1];
                    mma16816(acc[nt], ah[0], ah[1], ah[2], ah[3], b0h, b1h);
                    mma16816(acc[nt], al[0], al[1], al[2], al[3], b0h, b1h);
                }
            }
        }
    }

    int r0 = wm * 16 + (lane >> 2);
#pragma unroll
    for (int nt = 0; nt < 8; nt++) {
        int col = wn * 64 + nt * 8 + (lane & 3) * 2;
        float2 bias = *(const float2*)(dcn_b + col);
        float2 o0 = make_float2(acc[nt][0] + bias.x, acc[nt][1] + bias.y);
        float2 o1 = make_float2(acc[nt][2] + bias.x, acc[nt][3] + bias.y);
        *(float2*)&g_xd[img][n0 + r0][col] = o0;
        *(float2*)&g_xd[img][n0 + r0 + 8][col] = o1;
    }
}

// ------------------------------ K4: Gram partials G = Ud^T Vd ----------------
// 128-row chunks (4 x 32-row subtiles), 128 chunks per batch.
__global__ void k4_gpart() {
    __shared__ float Us[32][129];
    __shared__ float Vs[32][129];
    int b = blockIdx.y, chunk = blockIdx.x;
    int n0 = chunk * 128, t = threadIdx.x;
    int il = t & 15, jl = t >> 4;

    float acc[8][8];
#pragma unroll
    for (int ii = 0; ii < 8; ii++)
#pragma unroll
        for (int jj = 0; jj < 8; jj++) acc[ii][jj] = 0.f;
    float colsum = 0.f;

    for (int s = 0; s < 4; s++) {
        __syncthreads();
        for (int idx = t; idx < 32 * 128; idx += 256) {
            int cc = idx & 127, nl = idx >> 7;
            Us[nl][cc] = g_xd[b][n0 + s * 32 + nl][cc];
            Vs[nl][cc] = g_xd[2 + b][n0 + s * 32 + nl][cc];
        }
        __syncthreads();
#pragma unroll 4
        for (int nl = 0; nl < 32; nl++) {
            float av[8], bv[8];
#pragma unroll
            for (int ii = 0; ii < 8; ii++) av[ii] = Us[nl][il + 16 * ii];
#pragma unroll
            for (int jj = 0; jj < 8; jj++) bv[jj] = Vs[nl][jl + 16 * jj];
#pragma unroll
            for (int ii = 0; ii < 8; ii++)
#pragma unroll
                for (int jj = 0; jj < 8; jj++) acc[ii][jj] += av[ii] * bv[jj];
        }
        if (t < 128) {
            for (int nl = 0; nl < 32; nl++) colsum += Us[nl][t];
        } else {
            int cc = t - 128;
            for (int nl = 0; nl < 32; nl++) colsum += Vs[nl][cc];
        }
    }
    if (t < 128) g_sup[b][chunk][t] = colsum;
    else         g_svp[b][chunk][t - 128] = colsum;

    for (int g = 0; g < 4; g++) {
        __syncthreads();
#pragma unroll
        for (int jj = 0; jj < 8; jj++) {
            Us[il][jl + 16 * jj]      = acc[2 * g][jj];
            Us[16 + il][jl + 16 * jj] = acc[2 * g + 1][jj];
        }
        __syncthreads();
        for (int idx = t; idx < 32 * 128; idx += 256) {
            int j = idx & 127, r = idx >> 7;
            g_Gp[b][chunk][(32 * g + r) * 128 + j] = Us[r][j];
        }
    }
}

// ------------------------------ K4b: reduce partials -------------------------
__global__ void k4b_reduce() {
    int idx = blockIdx.x * 256 + threadIdx.x;
    if (idx < Bb * Cc * Cc) {
        int b = idx >> 14;
        int rem = idx & (Cc * Cc - 1);
        float s = 0.f;
        for (int ch = 0; ch < NCHUNK; ch++) s += g_Gp[b][ch][rem];
        g_G[b][rem] = s;
    } else {
        int k = idx - Bb * Cc * Cc;
        if (k < 2 * Bb * Cc) {
            int sel = k >> 8;
            int b = (k >> 7) & 1;
            int c = k & 127;
            float s = 0.f;
            if (sel) { for (int ch = 0; ch < NCHUNK; ch++) s += g_svp[b][ch][c]; g_sv[b][c] = s; }
            else     { for (int ch = 0; ch < NCHUNK; ch++) s += g_sup[b][ch][c]; g_su[b][c] = s; }
        }
    }
}

// ------------------------------ K5: tiny attention math ----------------------
__global__ void k5_attn(const float* __restrict__ q_w, const float* __restrict__ q_b,
                        const float* __restrict__ k_w, const float* __restrict__ k_b,
                        const float* __restrict__ v_w, const float* __restrict__ v_b) {
    __shared__ float P[4][128];
    __shared__ float L[4][128];
    __shared__ float ksv[128];
    __shared__ float qsu[4];
    int b = blockIdx.y;
    int i0 = blockIdx.x * 4;
    int t = threadIdx.x;
    int lane = t & 31, wid = t >> 5;

    if (t < 128) {
        float s = 0.f;
        for (int a = 0; a < 128; a++) s += k_w[t * 128 + a] * g_sv[b][a];
        ksv[t] = s;
    } else if (t < 132) {
        int i = i0 + (t - 128);
        float s = 0.f;
        for (int a = 0; a < 128; a++) s += q_w[i * 128 + a] * g_su[b][a];
        qsu[t - 128] = s;
    }
    __syncthreads();

    for (int idx = t; idx < 4 * 128; idx += 256) {
        int a = idx & 127, ii = idx >> 7;
        int i = i0 + ii;
        float s = 0.f;
        for (int m = 0; m < 128; m++) s += q_w[i * 128 + m] * g_G[b][m * 128 + a];
        P[ii][a] = s;
    }
    __syncthreads();

    const float scale = 0.088388347648318447f; // 128^-0.5
    for (int idx = t; idx < 4 * 128; idx += 256) {
        int j = idx & 127, ii = idx >> 7;
        int i = i0 + ii;
        float s = 0.f;
        for (int a = 0; a < 128; a++) s += P[ii][a] * k_w[j * 128 + a];
        s += qsu[ii] * k_b[j] + q_b[i] * ksv[j] + (float)Nn * q_b[i] * k_b[j];
        L[ii][j] = s * scale;
    }
    __syncthreads();

    if (wid < 4) {
        int r = wid;
        float v[4];
        float m = -1e30f;
#pragma unroll
        for (int q = 0; q < 4; q++) { v[q] = L[r][lane + 32 * q]; m = fmaxf(m, v[q]); }
#pragma unroll
        for (int o = 16; o > 0; o >>= 1) m = fmaxf(m, __shfl_xor_sync(0xFFFFFFFFu, m, o));
        float s = 0.f;
#pragma unroll
        for (int q = 0; q < 4; q++) { v[q] = expf(v[q] - m); s += v[q]; }
#pragma unroll
        for (int o = 16; o > 0; o >>= 1) s += __shfl_xor_sync(0xFFFFFFFFu, s, o);
        float inv = 1.f / s;
#pragma unroll
        for (int q = 0; q < 4; q++) L[r][lane + 32 * q] = v[q] * inv;
    }
    __syncthreads();

    for (int idx = t; idx < 4 * 128; idx += 256) {
        int m = idx & 127, ii = idx >> 7;
        float s = 0.f;
        for (int j = 0; j < 128; j++) s += L[ii][j] * v_w[j * 128 + m];
        g_Mt[b][m * 128 + (i0 + ii)] = s;
    }
    if (t < 4) {
        float s = 0.f;
        for (int j = 0; j < 128; j++) s += L[t][j] * v_b[j];
        g_r[b][i0 + t] = s;
    }
}

// ------------------------------ K6: out = M @ Vd^T + r -----------------------
__global__ void k6_out(float* __restrict__ out) {
    __shared__ float Ms[32][129];
    __shared__ float Vs[32][129];
    int b = blockIdx.y, n0 = blockIdx.x * 128, t = threadIdx.x;
    int il = t & 15, jl = t >> 4;

    float acc[8][8];
#pragma unroll
    for (int ii = 0; ii < 8; ii++)
#pragma unroll
        for (int jj = 0; jj < 8; jj++) acc[ii][jj] = 0.f;

    for (int s = 0; s < 4; s++) {
        __syncthreads();
        for (int idx = t; idx < 32 * 128; idx += 256) {
            int i = idx & 127, mm = idx >> 7;
            Ms[mm][i] = g_Mt[b][(s * 32 + mm) * 128 + i];
        }
        for (int idx = t; idx < 32 * 128; idx += 256) {
            int mmr = idx & 31, nl = idx >> 5;
            Vs[mmr][nl] = g_xd[2 + b][n0 + nl][s * 32 + mmr];
        }
        __syncthreads();
#pragma unroll 4
        for (int mm = 0; mm < 32; mm++) {
            float av[8], bv[8];
#pragma unroll
            for (int ii = 0; ii < 8; ii++) av[ii] = Ms[mm][il + 16 * ii];
#pragma unroll
            for (int jj = 0; jj < 8; jj++) bv[jj] = Vs[mm][jl + 16 * jj];
#pragma unroll
            for (int ii = 0; ii < 8; ii++)
#pragma unroll
                for (int jj = 0; jj < 8; jj++) acc[ii][jj] += av[ii] * bv[jj];
        }
    }

    for (int g = 0; g < 4; g++) {
        __syncthreads();
#pragma unroll
        for (int jj = 0; jj < 8; jj++) {
            Ms[il][jl + 16 * jj]      = acc[2 * g][jj];
            Ms[16 + il][jl + 16 * jj] = acc[2 * g + 1][jj];
        }
        __syncthreads();
        for (int idx = t; idx < 32 * 128; idx += 256) {
            int j = idx & 127, r = idx >> 7;
            int i = 32 * g + r;
            out[(size_t)(b * Cc + i) * Nn + n0 + j] = Ms[r][j] + g_r[b][i];
        }
    }
}

// ------------------------------ launch ---------------------------------------
extern "C" void kernel_launch(void* const* d_in, const int* in_sizes, int n_in,
                              void* d_out, int out_size) {
    (void)in_sizes; (void)n_in; (void)out_size;
    const float* u        = (const float*)d_in[0];
    const float* v        = (const float*)d_in[1];
    const float* offset_w = (const float*)d_in[2];
    const float* offset_b = (const float*)d_in[3];
    const float* dcn_w    = (const float*)d_in[4];
    const float* dcn_b    = (const float*)d_in[5];
    const float* q_w      = (const float*)d_in[6];
    const float* q_b      = (const float*)d_in[7];
    const float* k_w      = (const float*)d_in[8];
    const float* k_b      = (const float*)d_in[9];
    const float* v_w      = (const float*)d_in[10];
    const float* v_b      = (const float*)d_in[11];
    float* out = (float*)d_out;

    cudaFuncSetAttribute(k1_offset, cudaFuncAttributeMaxDynamicSharedMemorySize, K1_DYN);
    cudaFuncSetAttribute(k3_deform, cudaFuncAttributeMaxDynamicSharedMemorySize, K3_DYN);

    k0_prep<<<(KK9 * Cc * Cc + 255) / 256, 256>>>(dcn_w, offset_w);
    k2_transpose<<<dim3(Nn / 32, Cc / 32, NIMG), dim3(32, 8)>>>(u, v);
    k1_offset<<<dim3(Hh, NIMG), 256, K1_DYN>>>(offset_b);
    k3_deform<<<dim3(Nn / 64, NIMG), 256, K3_DYN>>>(dcn_b);
    k4_gpart<<<dim3(NCHUNK, Bb), 256>>>();
    k4b_reduce<<<130, 256>>>();
    k5_attn<<<dim3(32, Bb), 256>>>(q_w, q_b, k_w, k_b, v_w, v_b);
    k6_out<<<dim3(Nn / 128, Bb), 256>>>(out);
}